// round 10
// baseline (speedup 1.0000x reference)
#include <cuda_runtime.h>
#include <cuda_bf16.h>
#include <cuda_fp16.h>
#include <cstdint>

// Problem constants
#define BB   8
#define NTOK 4096
#define DMODEL 512
#define HH   8
#define DH   64
#define WW   128
#define PP   32
#define DISP 64

// ---------------------------------------------------------------------------
// Scratch (__device__ globals; allocation-free rule)
// ---------------------------------------------------------------------------
__device__ __nv_bfloat16 g_q0[BB*HH*PP*WW*DH];
__device__ __nv_bfloat16 g_q1[BB*HH*PP*WW*DH];
__device__ __nv_bfloat16 g_k0[BB*HH*PP*WW*DH];
__device__ __nv_bfloat16 g_k1[BB*HH*PP*WW*DH];
__device__ __nv_bfloat16 g_v0[BB*HH*PP*WW*DH];
__device__ __nv_bfloat16 g_v1[BB*HH*PP*WW*DH];
__device__ __half g_xa[BB*NTOK*DMODEL];
__device__ __half g_wq[3*HH*DH*DMODEL];
__device__ __half g_wo[DMODEL*DMODEL];
__device__ __half g_ao[BB*NTOK*DMODEL];

__device__ __forceinline__ uint32_t smem_u32(const void* p) {
    uint32_t a;
    asm("{ .reg .u64 t; cvta.to.shared.u64 t, %1; cvt.u32.u64 %0, t; }"
        : "=r"(a) : "l"(p));
    return a;
}
__device__ __forceinline__ void mma16816(float* d, const uint32_t* a,
                                         uint32_t b0, uint32_t b1) {
    asm volatile(
        "mma.sync.aligned.m16n8k16.row.col.f32.bf16.bf16.f32 "
        "{%0,%1,%2,%3}, {%4,%5,%6,%7}, {%8,%9}, {%0,%1,%2,%3};"
        : "+f"(d[0]), "+f"(d[1]), "+f"(d[2]), "+f"(d[3])
        : "r"(a[0]), "r"(a[1]), "r"(a[2]), "r"(a[3]), "r"(b0), "r"(b1));
}
__device__ __forceinline__ void mma16816h(float* d, const uint32_t* a,
                                          uint32_t b0, uint32_t b1) {
    asm volatile(
        "mma.sync.aligned.m16n8k16.row.col.f32.f16.f16.f32 "
        "{%0,%1,%2,%3}, {%4,%5,%6,%7}, {%8,%9}, {%0,%1,%2,%3};"
        : "+f"(d[0]), "+f"(d[1]), "+f"(d[2]), "+f"(d[3])
        : "r"(a[0]), "r"(a[1]), "r"(a[2]), "r"(a[3]), "r"(b0), "r"(b1));
}
__device__ __forceinline__ void ldsm_x4(uint32_t* r, uint32_t addr) {
    asm volatile("ldmatrix.sync.aligned.m8n8.x4.shared.b16 {%0,%1,%2,%3}, [%4];"
                 : "=r"(r[0]), "=r"(r[1]), "=r"(r[2]), "=r"(r[3]) : "r"(addr));
}
__device__ __forceinline__ void ldsm_x4t(uint32_t* r, uint32_t addr) {
    asm volatile("ldmatrix.sync.aligned.m8n8.x4.trans.shared.b16 {%0,%1,%2,%3}, [%4];"
                 : "=r"(r[0]), "=r"(r[1]), "=r"(r[2]), "=r"(r[3]) : "r"(addr));
}
__device__ __forceinline__ void pack_split(float x, float y, uint32_t& hi, uint32_t& lo) {
    __nv_bfloat16 hx = __float2bfloat16(x), hy = __float2bfloat16(y);
    float rx = x - __bfloat162float(hx), ry = y - __bfloat162float(hy);
    __nv_bfloat162 h; h.x = hx; h.y = hy;
    __nv_bfloat162 l; l.x = __float2bfloat16(rx); l.y = __float2bfloat16(ry);
    hi = *(uint32_t*)&h; lo = *(uint32_t*)&l;
}
__device__ __forceinline__ uint32_t pack_h2(float x, float y) {
    __half2 h; h.x = __float2half_rn(x); h.y = __float2half_rn(y);
    return *(uint32_t*)&h;
}

// ---------------------------------------------------------------------------
// Prepass
// ---------------------------------------------------------------------------
__global__ __launch_bounds__(256) void conv_x_kernel(const float* __restrict__ X) {
    int idx = blockIdx.x * 256 + threadIdx.x;
    if (idx >= BB * NTOK * DMODEL) return;
    int r = idx >> 9, k = idx & 511;
    int b = r >> 12, n = r & 4095;
    float v = X[(size_t)(b * NTOK + ((n + DISP) & 4095)) * DMODEL + k];
    g_xa[idx] = __float2half_rn(v);
}

__global__ __launch_bounds__(256) void conv_w_kernel(const float* __restrict__ src,
                                                     int N, int which) {
    int idx = blockIdx.x * 256 + threadIdx.x;
    if (idx >= N * DMODEL) return;
    int n = idx >> 9, k = idx & 511;
    float v = src[(size_t)k * N + n];
    if (which == 0) g_wq[idx] = __float2half_rn(v);
    else            g_wo[idx] = __float2half_rn(v);
}

// ---------------------------------------------------------------------------
// single-pass fp16 mma.sync GEMM with ldmatrix.x4 fragment loads.
// block tile 256x128, 8 warps (4x2) of 64x64. K=512 in 8 chunks of 64.
// ---------------------------------------------------------------------------
#define KCH   64
#define TSTR  72
#define TILE_A_E (256*TSTR)
#define TILE_B_E (128*TSTR)
#define STAGE_E  (TILE_A_E + TILE_B_E)
#define GEMM_SMEM (2*STAGE_E*2)             // 110592 B

__global__ __launch_bounds__(256) void gemm256(const float* __restrict__ bias,
                                               float* __restrict__ Out, int mode) {
    extern __shared__ char smem_raw[];
    __half* smem = (__half*)smem_raw;
    const int tid = threadIdx.x;
    const int wid = tid >> 5;
    const int lid = tid & 31;
    const int row0 = blockIdx.y * 256;
    const int col0 = blockIdx.x * 128;
    const int wm = wid & 3, wn = wid >> 2;
    const int g = lid >> 2, cq = lid & 3;

    const __half* A  = mode ? g_ao : g_xa;
    const __half* Bw = mode ? g_wo : g_wq;

    auto issue = [&](int ko, int buf) {
        const int kbase = ko * KCH;
        __half* st = smem + buf * STAGE_E;
#pragma unroll
        for (int i = 0; i < 12; i++) {
            const int cidx = tid + i * 256;
            const __half* src;
            uint32_t dst;
            if (cidx < 2048) {
                const int r = cidx >> 3;
                const int c8 = cidx & 7;
                src = A + (size_t)(row0 + r) * 512 + kbase + c8 * 8;
                dst = smem_u32(st + r * TSTR + c8 * 8);
            } else {
                const int rem = cidx - 2048;
                const int r = rem >> 3;
                const int c8 = rem & 7;
                src = Bw + (size_t)(col0 + r) * 512 + kbase + c8 * 8;
                dst = smem_u32(st + TILE_A_E + r * TSTR + c8 * 8);
            }
            asm volatile("cp.async.cg.shared.global [%0], [%1], 16;"
                         :: "r"(dst), "l"(src));
        }
        asm volatile("cp.async.commit_group;");
    };

    float acc[4][8][4];
#pragma unroll
    for (int im = 0; im < 4; im++)
#pragma unroll
        for (int in_ = 0; in_ < 8; in_++)
#pragma unroll
            for (int e = 0; e < 4; e++) acc[im][in_][e] = 0.f;

    // ldmatrix lane address pattern: lanes 0-7 -> rows 0-7 @k0, 8-15 -> rows 8-15 @k0,
    // 16-23 -> rows 0-7 @k+8, 24-31 -> rows 8-15 @k+8
    const int lrow = (lid & 7) + ((lid >> 3) & 1) * 8;
    const int lkad = (lid >> 4) * 8;
    const uint32_t smem0 = smem_u32(smem);
    // byte offsets within a stage
    const uint32_t aoffB = (uint32_t)(((wm * 64 + lrow) * TSTR + lkad) * 2);
    const uint32_t boffB = (uint32_t)((TILE_A_E + (wn * 64 + lrow) * TSTR + lkad) * 2);

    issue(0, 0);
    for (int ko = 0; ko < 8; ko++) {
        const int buf = ko & 1;
        if (ko + 1 < 8) {
            issue(ko + 1, buf ^ 1);
            asm volatile("cp.async.wait_group 1;");
        } else {
            asm volatile("cp.async.wait_group 0;");
        }
        __syncthreads();

        const uint32_t stB = smem0 + (uint32_t)(buf * STAGE_E * 2);
        const uint32_t aB = stB + aoffB;
        const uint32_t bB = stB + boffB;

#pragma unroll
        for (int ks = 0; ks < 4; ks++) {
            const uint32_t kofsB = ks * 32;          // 16 elems * 2B
            uint32_t af[4][4], bf[4][4];
#pragma unroll
            for (int im = 0; im < 4; im++)
                ldsm_x4(af[im], aB + im * (16 * TSTR * 2) + kofsB);
#pragma unroll
            for (int j = 0; j < 4; j++)
                ldsm_x4(bf[j], bB + j * (16 * TSTR * 2) + kofsB);
#pragma unroll
            for (int in_ = 0; in_ < 8; in_++) {
                const uint32_t b0 = bf[in_ >> 1][in_ & 1];
                const uint32_t b1 = bf[in_ >> 1][2 + (in_ & 1)];
#pragma unroll
                for (int im = 0; im < 4; im++)
                    mma16816h(acc[im][in_], af[im], b0, b1);
            }
        }
        __syncthreads();
    }

    // Epilogue
#pragma unroll
    for (int im = 0; im < 4; im++) {
#pragma unroll
        for (int in_ = 0; in_ < 8; in_++) {
            const int C0 = col0 + wn * 64 + in_ * 8 + cq * 2;
#pragma unroll
            for (int half = 0; half < 2; half++) {
                const int R = row0 + wm * 64 + im * 16 + g + half * 8;
                float vx = acc[im][in_][half * 2];
                float vy = acc[im][in_][half * 2 + 1];
                if (mode == 0) {
                    const int b2 = R >> 12, n2 = R & 4095;
                    const int w = n2 >> 5, jw = n2 & 31;
                    const int part = C0 >> 9;
                    const int h = (C0 & 511) >> 6;
                    const int dh = C0 & 63;
                    const size_t idx = (((size_t)((b2 * HH + h) * PP + jw)) * WW + w) * DH + dh;
                    uint32_t hi, lo;
                    pack_split(vx, vy, hi, lo);
                    __nv_bfloat16* d0 = (part == 0 ? g_q0 : part == 1 ? g_k0 : g_v0);
                    __nv_bfloat16* d1 = (part == 0 ? g_q1 : part == 1 ? g_k1 : g_v1);
                    *(uint32_t*)(d0 + idx) = hi;
                    *(uint32_t*)(d1 + idx) = lo;
                } else {
                    const int b2 = R >> 12, n2 = R & 4095;
                    const int dstn = (n2 + DISP) & 4095;
                    float2 v2;
                    v2.x = vx + __ldg(&bias[C0]);
                    v2.y = vy + __ldg(&bias[C0 + 1]);
                    *(float2*)(Out + (size_t)(b2 * NTOK + dstn) * DMODEL + C0) = v2;
                }
            }
        }
    }
}

// ---------------------------------------------------------------------------
// K2: tensor-core window attention (mask-split halves), bf16 3-pass,
// all fragment loads via ldmatrix.x4.
// ---------------------------------------------------------------------------
#define ATSTR 72
#define ATILE_E (WW*ATSTR)
#define ATILE_B (ATILE_E*2)
#define ATT_SMEM (1024 + 6*ATILE_B)          // 111616 B

__global__ __launch_bounds__(256) void attn_kernel(const float* __restrict__ pos_emb) {
    extern __shared__ char smem_raw[];
    float* slut = (float*)smem_raw;
    __nv_bfloat16* tiles = (__nv_bfloat16*)(smem_raw + 1024);

    const int bid = blockIdx.x;
    const int tid = threadIdx.x;
    const int wid = tid >> 5;
    const int lid = tid & 31;
    const int g = lid >> 2, cq = lid & 3;

    if (tid < 2 * WW - 1) slut[tid] = pos_emb[tid];

    const size_t woff = (size_t)bid * (WW * DH);
    const __nv_bfloat16* srcs[6] = { g_q0 + woff, g_q1 + woff, g_k0 + woff,
                                     g_k1 + woff, g_v0 + woff, g_v1 + woff };
#pragma unroll
    for (int arr = 0; arr < 6; arr++) {
        const __nv_bfloat16* src = srcs[arr];
        __nv_bfloat16* tb = tiles + arr * ATILE_E;
#pragma unroll
        for (int ii = 0; ii < 4; ii++) {
            const int idx = ii * 256 + tid;
            const int r = idx >> 3, c8 = idx & 7;
            const uint32_t dst = smem_u32(tb + r * ATSTR + c8 * 8);
            asm volatile("cp.async.cg.shared.global [%0], [%1], 16;"
                         :: "r"(dst), "l"(src + r * 64 + c8 * 8));
        }
    }
    asm volatile("cp.async.commit_group;");
    asm volatile("cp.async.wait_group 0;");
    __syncthreads();

    const uint32_t tiles0 = smem_u32(tiles);
    const uint32_t sq0B = tiles0;
    const uint32_t sq1B = tiles0 + ATILE_B;
    const uint32_t sk0B = tiles0 + 2 * ATILE_B;
    const uint32_t sk1B = tiles0 + 3 * ATILE_B;
    const uint32_t sv0B = tiles0 + 4 * ATILE_B;
    const uint32_t sv1B = tiles0 + 5 * ATILE_B;

    const int half = wid >> 2;
    const int mrow = (wid & 3) * 16;
    const int qrow0 = half * 64 + mrow;
    const int kbase = half * 64;

    const int lrow = (lid & 7) + ((lid >> 3) & 1) * 8;
    const int lkad = (lid >> 4) * 8;
    // Q fragment address (per-ks add kofs)
    const uint32_t qadd = (uint32_t)(((qrow0 + lrow) * ATSTR + lkad) * 2);
    // K fragment base (j-th 16-row block adds j*16*ATSTR)
    const uint32_t kadd = (uint32_t)(((kbase + lrow) * ATSTR + lkad) * 2);
    // V trans pattern: lanes 0-15 rows k0-15 @ col base; lanes 16-31 same rows @ col+8
    const int vlrow = lid & 15;
    const int vcol = (lid >> 4) * 8;

    float S[8][4];
#pragma unroll
    for (int nt = 0; nt < 8; nt++)
#pragma unroll
        for (int e = 0; e < 4; e++) S[nt][e] = 0.f;

#pragma unroll
    for (int ks = 0; ks < 4; ks++) {
        const uint32_t kofsB = ks * 32;
        uint32_t aq0[4], aq1[4], kb0[4][4], kb1[4][4];
        ldsm_x4(aq0, sq0B + qadd + kofsB);
        ldsm_x4(aq1, sq1B + qadd + kofsB);
#pragma unroll
        for (int j = 0; j < 4; j++) {
            ldsm_x4(kb0[j], sk0B + kadd + j * (16 * ATSTR * 2) + kofsB);
            ldsm_x4(kb1[j], sk1B + kadd + j * (16 * ATSTR * 2) + kofsB);
        }
#pragma unroll
        for (int nt = 0; nt < 8; nt++) {
            const uint32_t b00 = kb0[nt >> 1][nt & 1];
            const uint32_t b01 = kb0[nt >> 1][2 + (nt & 1)];
            const uint32_t b10 = kb1[nt >> 1][nt & 1];
            const uint32_t b11 = kb1[nt >> 1][2 + (nt & 1)];
            mma16816(S[nt], aq0, b00, b01);
            mma16816(S[nt], aq0, b10, b11);
            mma16816(S[nt], aq1, b00, b01);
        }
    }

    const float scale = 0.125f;
    const int il0 = mrow + g;
    const int il1 = il0 + 8;
    float rs0 = 0.f, rs1 = 0.f;
#pragma unroll
    for (int nt = 0; nt < 8; nt++) {
        const int jl = nt * 8 + cq * 2;
        float p0 = __expf(S[nt][0] * scale + slut[jl - il0 + (WW - 1)]);
        float p1 = __expf(S[nt][1] * scale + slut[jl + 1 - il0 + (WW - 1)]);
        float p2 = __expf(S[nt][2] * scale + slut[jl - il1 + (WW - 1)]);
        float p3 = __expf(S[nt][3] * scale + slut[jl + 1 - il1 + (WW - 1)]);
        S[nt][0] = p0; S[nt][1] = p1; S[nt][2] = p2; S[nt][3] = p3;
        rs0 += p0 + p1;
        rs1 += p2 + p3;
    }
    rs0 += __shfl_xor_sync(0xFFFFFFFF, rs0, 1);
    rs0 += __shfl_xor_sync(0xFFFFFFFF, rs0, 2);
    rs1 += __shfl_xor_sync(0xFFFFFFFF, rs1, 1);
    rs1 += __shfl_xor_sync(0xFFFFFFFF, rs1, 2);
    const float inv0 = 1.0f / rs0;
    const float inv1 = 1.0f / rs1;

    uint32_t p0f[4][4], p1f[4][4];
#pragma unroll
    for (int ks = 0; ks < 4; ks++) {
        pack_split(S[2 * ks][0],     S[2 * ks][1],     p0f[ks][0], p1f[ks][0]);
        pack_split(S[2 * ks][2],     S[2 * ks][3],     p0f[ks][1], p1f[ks][1]);
        pack_split(S[2 * ks + 1][0], S[2 * ks + 1][1], p0f[ks][2], p1f[ks][2]);
        pack_split(S[2 * ks + 1][2], S[2 * ks + 1][3], p0f[ks][3], p1f[ks][3]);
    }

    float O[8][4];
#pragma unroll
    for (int nt = 0; nt < 8; nt++)
#pragma unroll
        for (int e = 0; e < 4; e++) O[nt][e] = 0.f;

#pragma unroll
    for (int ks = 0; ks < 4; ks++) {
        const int vrow16 = kbase + ks * 16 + vlrow;
#pragma unroll
        for (int j = 0; j < 4; j++) {
            // x4.trans: covers nt=2j (cols j*16..+7) and nt=2j+1 (cols +8..15)
            uint32_t v0[4], v1[4];
            const uint32_t vaddr = (uint32_t)((vrow16 * ATSTR + j * 16 + vcol) * 2);
            ldsm_x4t(v0, sv0B + vaddr);
            ldsm_x4t(v1, sv1B + vaddr);
            mma16816(O[2 * j],     p0f[ks], v0[0], v0[1]);
            mma16816(O[2 * j],     p0f[ks], v1[0], v1[1]);
            mma16816(O[2 * j],     p1f[ks], v0[0], v0[1]);
            mma16816(O[2 * j + 1], p0f[ks], v0[2], v0[3]);
            mma16816(O[2 * j + 1], p0f[ks], v1[2], v1[3]);
            mma16816(O[2 * j + 1], p1f[ks], v0[2], v0[3]);
        }
    }

    const int b  = bid >> 8;
    const int h  = (bid >> 5) & 7;
    const int jw = bid & 31;
    const int iw0 = half * 64 + il0;
    const int iw1 = half * 64 + il1;
    const size_t row0off = ((size_t)(b * NTOK + jw * WW + iw0)) * DMODEL + h * DH;
    const size_t row1off = ((size_t)(b * NTOK + jw * WW + iw1)) * DMODEL + h * DH;
#pragma unroll
    for (int nt = 0; nt < 8; nt++) {
        const int c = nt * 8 + cq * 2;
        *(uint32_t*)(g_ao + row0off + c) = pack_h2(O[nt][0] * inv0, O[nt][1] * inv0);
        *(uint32_t*)(g_ao + row1off + c) = pack_h2(O[nt][2] * inv1, O[nt][3] * inv1);
    }
}

// ---------------------------------------------------------------------------
extern "C" void kernel_launch(void* const* d_in, const int* in_sizes, int n_in,
                              void* d_out, int out_size) {
    const float* x       = (const float*)d_in[0];
    const float* Wqkv    = (const float*)d_in[1];
    const float* pos_emb = (const float*)d_in[2];
    const float* Wout    = (const float*)d_in[3];
    const float* bout    = (const float*)d_in[4];
    float* out = (float*)d_out;

    cudaFuncSetAttribute(gemm256, cudaFuncAttributeMaxDynamicSharedMemorySize, GEMM_SMEM);
    cudaFuncSetAttribute(attn_kernel, cudaFuncAttributeMaxDynamicSharedMemorySize, ATT_SMEM);

    conv_x_kernel<<<(BB * NTOK * DMODEL + 255) / 256, 256>>>(x);
    conv_w_kernel<<<(1536 * 512 + 255) / 256, 256>>>(Wqkv, 1536, 0);
    conv_w_kernel<<<(512 * 512 + 255) / 256, 256>>>(Wout, 512, 1);

    // K1: QKV (M=32768 -> 128 row blocks, N=1536 -> 12 col blocks)
    gemm256<<<dim3(12, 128), 256, GEMM_SMEM>>>(nullptr, nullptr, 0);
    // K2: attention, one window per block
    attn_kernel<<<2048, 256, ATT_SMEM>>>(pos_emb);
    // K3: output projection (N=512 -> 4 col blocks) + bias + roll
    gemm256<<<dim3(4, 128), 256, GEMM_SMEM>>>(bout, out, 1);
}

// round 11
// speedup vs baseline: 1.0153x; 1.0153x over previous
#include <cuda_runtime.h>
#include <cuda_bf16.h>
#include <cuda_fp16.h>
#include <cstdint>

// Problem constants
#define BB   8
#define NTOK 4096
#define DMODEL 512
#define HH   8
#define DH   64
#define WW   128
#define PP   32
#define DISP 64

// ---------------------------------------------------------------------------
// Scratch (__device__ globals; allocation-free rule)
// ---------------------------------------------------------------------------
__device__ __nv_bfloat16 g_q0[BB*HH*PP*WW*DH];
__device__ __nv_bfloat16 g_q1[BB*HH*PP*WW*DH];
__device__ __nv_bfloat16 g_k0[BB*HH*PP*WW*DH];
__device__ __nv_bfloat16 g_k1[BB*HH*PP*WW*DH];
__device__ __nv_bfloat16 g_v0[BB*HH*PP*WW*DH];
__device__ __nv_bfloat16 g_v1[BB*HH*PP*WW*DH];
__device__ __half g_xa[BB*NTOK*DMODEL];
__device__ __half g_wq[3*HH*DH*DMODEL];
__device__ __half g_wo[DMODEL*DMODEL];
__device__ __half g_ao[BB*NTOK*DMODEL];

__device__ __forceinline__ uint32_t smem_u32(const void* p) {
    uint32_t a;
    asm("{ .reg .u64 t; cvta.to.shared.u64 t, %1; cvt.u32.u64 %0, t; }"
        : "=r"(a) : "l"(p));
    return a;
}
__device__ __forceinline__ void mma16816(float* d, const uint32_t* a,
                                         uint32_t b0, uint32_t b1) {
    asm volatile(
        "mma.sync.aligned.m16n8k16.row.col.f32.bf16.bf16.f32 "
        "{%0,%1,%2,%3}, {%4,%5,%6,%7}, {%8,%9}, {%0,%1,%2,%3};"
        : "+f"(d[0]), "+f"(d[1]), "+f"(d[2]), "+f"(d[3])
        : "r"(a[0]), "r"(a[1]), "r"(a[2]), "r"(a[3]), "r"(b0), "r"(b1));
}
__device__ __forceinline__ void mma16816h(float* d, const uint32_t* a,
                                          uint32_t b0, uint32_t b1) {
    asm volatile(
        "mma.sync.aligned.m16n8k16.row.col.f32.f16.f16.f32 "
        "{%0,%1,%2,%3}, {%4,%5,%6,%7}, {%8,%9}, {%0,%1,%2,%3};"
        : "+f"(d[0]), "+f"(d[1]), "+f"(d[2]), "+f"(d[3])
        : "r"(a[0]), "r"(a[1]), "r"(a[2]), "r"(a[3]), "r"(b0), "r"(b1));
}
__device__ __forceinline__ void ldsm_x4(uint32_t* r, uint32_t addr) {
    asm volatile("ldmatrix.sync.aligned.m8n8.x4.shared.b16 {%0,%1,%2,%3}, [%4];"
                 : "=r"(r[0]), "=r"(r[1]), "=r"(r[2]), "=r"(r[3]) : "r"(addr));
}
__device__ __forceinline__ void ldsm_x4t(uint32_t* r, uint32_t addr) {
    asm volatile("ldmatrix.sync.aligned.m8n8.x4.trans.shared.b16 {%0,%1,%2,%3}, [%4];"
                 : "=r"(r[0]), "=r"(r[1]), "=r"(r[2]), "=r"(r[3]) : "r"(addr));
}
__device__ __forceinline__ void pack_split(float x, float y, uint32_t& hi, uint32_t& lo) {
    __nv_bfloat16 hx = __float2bfloat16(x), hy = __float2bfloat16(y);
    float rx = x - __bfloat162float(hx), ry = y - __bfloat162float(hy);
    __nv_bfloat162 h; h.x = hx; h.y = hy;
    __nv_bfloat162 l; l.x = __float2bfloat16(rx); l.y = __float2bfloat16(ry);
    hi = *(uint32_t*)&h; lo = *(uint32_t*)&l;
}
__device__ __forceinline__ uint32_t pack_h2(float x, float y) {
    __half2 h; h.x = __float2half_rn(x); h.y = __float2half_rn(y);
    return *(uint32_t*)&h;
}

// ---------------------------------------------------------------------------
// Prepass
// ---------------------------------------------------------------------------
__global__ __launch_bounds__(256) void conv_x_kernel(const float* __restrict__ X) {
    int idx = blockIdx.x * 256 + threadIdx.x;
    if (idx >= BB * NTOK * DMODEL) return;
    int r = idx >> 9, k = idx & 511;
    int b = r >> 12, n = r & 4095;
    float v = X[(size_t)(b * NTOK + ((n + DISP) & 4095)) * DMODEL + k];
    g_xa[idx] = __float2half_rn(v);
}

__global__ __launch_bounds__(256) void conv_w_kernel(const float* __restrict__ src,
                                                     int N, int which) {
    int idx = blockIdx.x * 256 + threadIdx.x;
    if (idx >= N * DMODEL) return;
    int n = idx >> 9, k = idx & 511;
    float v = src[(size_t)k * N + n];
    if (which == 0) g_wq[idx] = __float2half_rn(v);
    else            g_wo[idx] = __float2half_rn(v);
}

// ---------------------------------------------------------------------------
// single-pass fp16 mma.sync GEMM. Block tile 256x128, 8 warps (4x2) of 64x64.
// K=512 in 4 chunks of 128 (fewer chunks -> fewer sync/wait envelopes).
// Scalar LDS fragment loads (measured faster than ldmatrix here).
// ---------------------------------------------------------------------------
#define KCH   128
#define TSTR  136                           // 128 + 8 pad
#define TILE_A_E (256*TSTR)                 // 34816 elems
#define TILE_B_E (128*TSTR)                 // 17408 elems
#define STAGE_E  (TILE_A_E + TILE_B_E)      // 52224 elems
#define GEMM_SMEM (2*STAGE_E*2)             // 208896 B

__global__ __launch_bounds__(256) void gemm256(const float* __restrict__ bias,
                                               float* __restrict__ Out, int mode) {
    extern __shared__ char smem_raw[];
    __half* smem = (__half*)smem_raw;
    const int tid = threadIdx.x;
    const int wid = tid >> 5;
    const int lid = tid & 31;
    const int row0 = blockIdx.y * 256;
    const int col0 = blockIdx.x * 128;
    const int wm = wid & 3, wn = wid >> 2;
    const int g = lid >> 2, cq = lid & 3;

    const __half* A  = mode ? g_ao : g_xa;
    const __half* Bw = mode ? g_wo : g_wq;

    // one 128-wide k-chunk: A 256 rows x 16 16B-chunks + B 128 x 16 = 6144
    auto issue = [&](int ko, int buf) {
        const int kbase = ko * KCH;
        __half* st = smem + buf * STAGE_E;
#pragma unroll
        for (int i = 0; i < 24; i++) {
            const int cidx = tid + i * 256;          // 0..6143
            const __half* src;
            uint32_t dst;
            if (cidx < 4096) {
                const int r = cidx >> 4;
                const int c8 = cidx & 15;
                src = A + (size_t)(row0 + r) * 512 + kbase + c8 * 8;
                dst = smem_u32(st + r * TSTR + c8 * 8);
            } else {
                const int rem = cidx - 4096;
                const int r = rem >> 4;
                const int c8 = rem & 15;
                src = Bw + (size_t)(col0 + r) * 512 + kbase + c8 * 8;
                dst = smem_u32(st + TILE_A_E + r * TSTR + c8 * 8);
            }
            asm volatile("cp.async.cg.shared.global [%0], [%1], 16;"
                         :: "r"(dst), "l"(src));
        }
        asm volatile("cp.async.commit_group;");
    };

    float acc[4][8][4];
#pragma unroll
    for (int im = 0; im < 4; im++)
#pragma unroll
        for (int in_ = 0; in_ < 8; in_++)
#pragma unroll
            for (int e = 0; e < 4; e++) acc[im][in_][e] = 0.f;

    issue(0, 0);
    for (int ko = 0; ko < 4; ko++) {
        const int buf = ko & 1;
        if (ko + 1 < 4) {
            issue(ko + 1, buf ^ 1);
            asm volatile("cp.async.wait_group 1;");
        } else {
            asm volatile("cp.async.wait_group 0;");
        }
        __syncthreads();

        const __half* Ap = smem + buf * STAGE_E;
        const __half* Bp = Ap + TILE_A_E;

#pragma unroll
        for (int ks = 0; ks < 8; ks++) {
            const int kofs = ks * 16;
            uint32_t af[4][4];
#pragma unroll
            for (int im = 0; im < 4; im++) {
                const int rb = wm * 64 + im * 16 + g;
                af[im][0] = *(const uint32_t*)(Ap + rb * TSTR + kofs + cq * 2);
                af[im][1] = *(const uint32_t*)(Ap + (rb + 8) * TSTR + kofs + cq * 2);
                af[im][2] = *(const uint32_t*)(Ap + rb * TSTR + kofs + 8 + cq * 2);
                af[im][3] = *(const uint32_t*)(Ap + (rb + 8) * TSTR + kofs + 8 + cq * 2);
            }
#pragma unroll
            for (int in_ = 0; in_ < 8; in_++) {
                const int nr = wn * 64 + in_ * 8 + g;
                const uint32_t b0 = *(const uint32_t*)(Bp + nr * TSTR + kofs + cq * 2);
                const uint32_t b1 = *(const uint32_t*)(Bp + nr * TSTR + kofs + 8 + cq * 2);
#pragma unroll
                for (int im = 0; im < 4; im++)
                    mma16816h(acc[im][in_], af[im], b0, b1);
            }
        }
        __syncthreads();
    }

    // Epilogue
#pragma unroll
    for (int im = 0; im < 4; im++) {
#pragma unroll
        for (int in_ = 0; in_ < 8; in_++) {
            const int C0 = col0 + wn * 64 + in_ * 8 + cq * 2;
#pragma unroll
            for (int half = 0; half < 2; half++) {
                const int R = row0 + wm * 64 + im * 16 + g + half * 8;
                float vx = acc[im][in_][half * 2];
                float vy = acc[im][in_][half * 2 + 1];
                if (mode == 0) {
                    const int b2 = R >> 12, n2 = R & 4095;
                    const int w = n2 >> 5, jw = n2 & 31;
                    const int part = C0 >> 9;
                    const int h = (C0 & 511) >> 6;
                    const int dh = C0 & 63;
                    const size_t idx = (((size_t)((b2 * HH + h) * PP + jw)) * WW + w) * DH + dh;
                    uint32_t hi, lo;
                    pack_split(vx, vy, hi, lo);
                    __nv_bfloat16* d0 = (part == 0 ? g_q0 : part == 1 ? g_k0 : g_v0);
                    __nv_bfloat16* d1 = (part == 0 ? g_q1 : part == 1 ? g_k1 : g_v1);
                    *(uint32_t*)(d0 + idx) = hi;
                    *(uint32_t*)(d1 + idx) = lo;
                } else {
                    const int b2 = R >> 12, n2 = R & 4095;
                    const int dstn = (n2 + DISP) & 4095;
                    float2 v2;
                    v2.x = vx + __ldg(&bias[C0]);
                    v2.y = vy + __ldg(&bias[C0 + 1]);
                    *(float2*)(Out + (size_t)(b2 * NTOK + dstn) * DMODEL + C0) = v2;
                }
            }
        }
    }
}

// ---------------------------------------------------------------------------
// K2: tensor-core window attention (mask-split halves), bf16 3-pass,
// fragment loads via ldmatrix.x4 (R10 version, measured neutral).
// ---------------------------------------------------------------------------
#define ATSTR 72
#define ATILE_E (WW*ATSTR)
#define ATILE_B (ATILE_E*2)
#define ATT_SMEM (1024 + 6*ATILE_B)          // 111616 B

__global__ __launch_bounds__(256) void attn_kernel(const float* __restrict__ pos_emb) {
    extern __shared__ char smem_raw[];
    float* slut = (float*)smem_raw;
    __nv_bfloat16* tiles = (__nv_bfloat16*)(smem_raw + 1024);

    const int bid = blockIdx.x;
    const int tid = threadIdx.x;
    const int wid = tid >> 5;
    const int lid = tid & 31;
    const int g = lid >> 2, cq = lid & 3;

    if (tid < 2 * WW - 1) slut[tid] = pos_emb[tid];

    const size_t woff = (size_t)bid * (WW * DH);
    const __nv_bfloat16* srcs[6] = { g_q0 + woff, g_q1 + woff, g_k0 + woff,
                                     g_k1 + woff, g_v0 + woff, g_v1 + woff };
#pragma unroll
    for (int arr = 0; arr < 6; arr++) {
        const __nv_bfloat16* src = srcs[arr];
        __nv_bfloat16* tb = tiles + arr * ATILE_E;
#pragma unroll
        for (int ii = 0; ii < 4; ii++) {
            const int idx = ii * 256 + tid;
            const int r = idx >> 3, c8 = idx & 7;
            const uint32_t dst = smem_u32(tb + r * ATSTR + c8 * 8);
            asm volatile("cp.async.cg.shared.global [%0], [%1], 16;"
                         :: "r"(dst), "l"(src + r * 64 + c8 * 8));
        }
    }
    asm volatile("cp.async.commit_group;");
    asm volatile("cp.async.wait_group 0;");
    __syncthreads();

    const uint32_t tiles0 = smem_u32(tiles);
    const uint32_t sq0B = tiles0;
    const uint32_t sq1B = tiles0 + ATILE_B;
    const uint32_t sk0B = tiles0 + 2 * ATILE_B;
    const uint32_t sk1B = tiles0 + 3 * ATILE_B;
    const uint32_t sv0B = tiles0 + 4 * ATILE_B;
    const uint32_t sv1B = tiles0 + 5 * ATILE_B;

    const int half = wid >> 2;
    const int mrow = (wid & 3) * 16;
    const int qrow0 = half * 64 + mrow;
    const int kbase = half * 64;

    const int lrow = (lid & 7) + ((lid >> 3) & 1) * 8;
    const int lkad = (lid >> 4) * 8;
    const uint32_t qadd = (uint32_t)(((qrow0 + lrow) * ATSTR + lkad) * 2);
    const uint32_t kadd = (uint32_t)(((kbase + lrow) * ATSTR + lkad) * 2);
    const int vlrow = lid & 15;
    const int vcol = (lid >> 4) * 8;

    float S[8][4];
#pragma unroll
    for (int nt = 0; nt < 8; nt++)
#pragma unroll
        for (int e = 0; e < 4; e++) S[nt][e] = 0.f;

#pragma unroll
    for (int ks = 0; ks < 4; ks++) {
        const uint32_t kofsB = ks * 32;
        uint32_t aq0[4], aq1[4], kb0[4][4], kb1[4][4];
        ldsm_x4(aq0, sq0B + qadd + kofsB);
        ldsm_x4(aq1, sq1B + qadd + kofsB);
#pragma unroll
        for (int j = 0; j < 4; j++) {
            ldsm_x4(kb0[j], sk0B + kadd + j * (16 * ATSTR * 2) + kofsB);
            ldsm_x4(kb1[j], sk1B + kadd + j * (16 * ATSTR * 2) + kofsB);
        }
#pragma unroll
        for (int nt = 0; nt < 8; nt++) {
            const uint32_t b00 = kb0[nt >> 1][nt & 1];
            const uint32_t b01 = kb0[nt >> 1][2 + (nt & 1)];
            const uint32_t b10 = kb1[nt >> 1][nt & 1];
            const uint32_t b11 = kb1[nt >> 1][2 + (nt & 1)];
            mma16816(S[nt], aq0, b00, b01);
            mma16816(S[nt], aq0, b10, b11);
            mma16816(S[nt], aq1, b00, b01);
        }
    }

    const float scale = 0.125f;
    const int il0 = mrow + g;
    const int il1 = il0 + 8;
    float rs0 = 0.f, rs1 = 0.f;
#pragma unroll
    for (int nt = 0; nt < 8; nt++) {
        const int jl = nt * 8 + cq * 2;
        float p0 = __expf(S[nt][0] * scale + slut[jl - il0 + (WW - 1)]);
        float p1 = __expf(S[nt][1] * scale + slut[jl + 1 - il0 + (WW - 1)]);
        float p2 = __expf(S[nt][2] * scale + slut[jl - il1 + (WW - 1)]);
        float p3 = __expf(S[nt][3] * scale + slut[jl + 1 - il1 + (WW - 1)]);
        S[nt][0] = p0; S[nt][1] = p1; S[nt][2] = p2; S[nt][3] = p3;
        rs0 += p0 + p1;
        rs1 += p2 + p3;
    }
    rs0 += __shfl_xor_sync(0xFFFFFFFF, rs0, 1);
    rs0 += __shfl_xor_sync(0xFFFFFFFF, rs0, 2);
    rs1 += __shfl_xor_sync(0xFFFFFFFF, rs1, 1);
    rs1 += __shfl_xor_sync(0xFFFFFFFF, rs1, 2);
    const float inv0 = 1.0f / rs0;
    const float inv1 = 1.0f / rs1;

    uint32_t p0f[4][4], p1f[4][4];
#pragma unroll
    for (int ks = 0; ks < 4; ks++) {
        pack_split(S[2 * ks][0],     S[2 * ks][1],     p0f[ks][0], p1f[ks][0]);
        pack_split(S[2 * ks][2],     S[2 * ks][3],     p0f[ks][1], p1f[ks][1]);
        pack_split(S[2 * ks + 1][0], S[2 * ks + 1][1], p0f[ks][2], p1f[ks][2]);
        pack_split(S[2 * ks + 1][2], S[2 * ks + 1][3], p0f[ks][3], p1f[ks][3]);
    }

    float O[8][4];
#pragma unroll
    for (int nt = 0; nt < 8; nt++)
#pragma unroll
        for (int e = 0; e < 4; e++) O[nt][e] = 0.f;

#pragma unroll
    for (int ks = 0; ks < 4; ks++) {
        const int vrow16 = kbase + ks * 16 + vlrow;
#pragma unroll
        for (int j = 0; j < 4; j++) {
            uint32_t v0[4], v1[4];
            const uint32_t vaddr = (uint32_t)((vrow16 * ATSTR + j * 16 + vcol) * 2);
            ldsm_x4t(v0, sv0B + vaddr);
            ldsm_x4t(v1, sv1B + vaddr);
            mma16816(O[2 * j],     p0f[ks], v0[0], v0[1]);
            mma16816(O[2 * j],     p0f[ks], v1[0], v1[1]);
            mma16816(O[2 * j],     p1f[ks], v0[0], v0[1]);
            mma16816(O[2 * j + 1], p0f[ks], v0[2], v0[3]);
            mma16816(O[2 * j + 1], p0f[ks], v1[2], v1[3]);
            mma16816(O[2 * j + 1], p1f[ks], v0[2], v0[3]);
        }
    }

    const int b  = bid >> 8;
    const int h  = (bid >> 5) & 7;
    const int jw = bid & 31;
    const int iw0 = half * 64 + il0;
    const int iw1 = half * 64 + il1;
    const size_t row0off = ((size_t)(b * NTOK + jw * WW + iw0)) * DMODEL + h * DH;
    const size_t row1off = ((size_t)(b * NTOK + jw * WW + iw1)) * DMODEL + h * DH;
#pragma unroll
    for (int nt = 0; nt < 8; nt++) {
        const int c = nt * 8 + cq * 2;
        *(uint32_t*)(g_ao + row0off + c) = pack_h2(O[nt][0] * inv0, O[nt][1] * inv0);
        *(uint32_t*)(g_ao + row1off + c) = pack_h2(O[nt][2] * inv1, O[nt][3] * inv1);
    }
}

// ---------------------------------------------------------------------------
extern "C" void kernel_launch(void* const* d_in, const int* in_sizes, int n_in,
                              void* d_out, int out_size) {
    const float* x       = (const float*)d_in[0];
    const float* Wqkv    = (const float*)d_in[1];
    const float* pos_emb = (const float*)d_in[2];
    const float* Wout    = (const float*)d_in[3];
    const float* bout    = (const float*)d_in[4];
    float* out = (float*)d_out;

    cudaFuncSetAttribute(gemm256, cudaFuncAttributeMaxDynamicSharedMemorySize, GEMM_SMEM);
    cudaFuncSetAttribute(attn_kernel, cudaFuncAttributeMaxDynamicSharedMemorySize, ATT_SMEM);

    conv_x_kernel<<<(BB * NTOK * DMODEL + 255) / 256, 256>>>(x);
    conv_w_kernel<<<(1536 * 512 + 255) / 256, 256>>>(Wqkv, 1536, 0);
    conv_w_kernel<<<(512 * 512 + 255) / 256, 256>>>(Wout, 512, 1);

    // K1: QKV (M=32768 -> 128 row blocks, N=1536 -> 12 col blocks)
    gemm256<<<dim3(12, 128), 256, GEMM_SMEM>>>(nullptr, nullptr, 0);
    // K2: attention, one window per block
    attn_kernel<<<2048, 256, ATT_SMEM>>>(pos_emb);
    // K3: output projection (N=512 -> 4 col blocks) + bias + roll
    gemm256<<<dim3(4, 128), 256, GEMM_SMEM>>>(bout, out, 1);
}

// round 12
// speedup vs baseline: 1.0934x; 1.0770x over previous
#include <cuda_runtime.h>
#include <cuda_bf16.h>
#include <cuda_fp16.h>
#include <cstdint>

// Problem constants
#define BB   8
#define NTOK 4096
#define DMODEL 512
#define HH   8
#define DH   64
#define WW   128
#define PP   32
#define DISP 64

// ---------------------------------------------------------------------------
// Scratch (__device__ globals; allocation-free rule)
// ---------------------------------------------------------------------------
__device__ __nv_bfloat16 g_q0[BB*HH*PP*WW*DH];
__device__ __nv_bfloat16 g_q1[BB*HH*PP*WW*DH];
__device__ __nv_bfloat16 g_k0[BB*HH*PP*WW*DH];
__device__ __nv_bfloat16 g_k1[BB*HH*PP*WW*DH];
__device__ __half        g_v [BB*HH*PP*WW*DH];   // single fp16 V
__device__ __half g_xa[BB*NTOK*DMODEL];
__device__ __half g_wq[3*HH*DH*DMODEL];
__device__ __half g_wo[DMODEL*DMODEL];
__device__ __half g_ao[BB*NTOK*DMODEL];

__device__ __forceinline__ uint32_t smem_u32(const void* p) {
    uint32_t a;
    asm("{ .reg .u64 t; cvta.to.shared.u64 t, %1; cvt.u32.u64 %0, t; }"
        : "=r"(a) : "l"(p));
    return a;
}
__device__ __forceinline__ void mma16816(float* d, const uint32_t* a,
                                         uint32_t b0, uint32_t b1) {
    asm volatile(
        "mma.sync.aligned.m16n8k16.row.col.f32.bf16.bf16.f32 "
        "{%0,%1,%2,%3}, {%4,%5,%6,%7}, {%8,%9}, {%0,%1,%2,%3};"
        : "+f"(d[0]), "+f"(d[1]), "+f"(d[2]), "+f"(d[3])
        : "r"(a[0]), "r"(a[1]), "r"(a[2]), "r"(a[3]), "r"(b0), "r"(b1));
}
__device__ __forceinline__ void mma16816h(float* d, const uint32_t* a,
                                          uint32_t b0, uint32_t b1) {
    asm volatile(
        "mma.sync.aligned.m16n8k16.row.col.f32.f16.f16.f32 "
        "{%0,%1,%2,%3}, {%4,%5,%6,%7}, {%8,%9}, {%0,%1,%2,%3};"
        : "+f"(d[0]), "+f"(d[1]), "+f"(d[2]), "+f"(d[3])
        : "r"(a[0]), "r"(a[1]), "r"(a[2]), "r"(a[3]), "r"(b0), "r"(b1));
}
__device__ __forceinline__ void ldsm_x4(uint32_t* r, uint32_t addr) {
    asm volatile("ldmatrix.sync.aligned.m8n8.x4.shared.b16 {%0,%1,%2,%3}, [%4];"
                 : "=r"(r[0]), "=r"(r[1]), "=r"(r[2]), "=r"(r[3]) : "r"(addr));
}
__device__ __forceinline__ void ldsm_x4t(uint32_t* r, uint32_t addr) {
    asm volatile("ldmatrix.sync.aligned.m8n8.x4.trans.shared.b16 {%0,%1,%2,%3}, [%4];"
                 : "=r"(r[0]), "=r"(r[1]), "=r"(r[2]), "=r"(r[3]) : "r"(addr));
}
__device__ __forceinline__ void pack_split(float x, float y, uint32_t& hi, uint32_t& lo) {
    __nv_bfloat16 hx = __float2bfloat16(x), hy = __float2bfloat16(y);
    float rx = x - __bfloat162float(hx), ry = y - __bfloat162float(hy);
    __nv_bfloat162 h; h.x = hx; h.y = hy;
    __nv_bfloat162 l; l.x = __float2bfloat16(rx); l.y = __float2bfloat16(ry);
    hi = *(uint32_t*)&h; lo = *(uint32_t*)&l;
}
__device__ __forceinline__ uint32_t pack_h2(float x, float y) {
    __half2 h; h.x = __float2half_rn(x); h.y = __float2half_rn(y);
    return *(uint32_t*)&h;
}

// ---------------------------------------------------------------------------
// Fused prepass: X roll+fp16, Wqkv^T fp16, Wout^T fp16, one linear dispatch.
// ---------------------------------------------------------------------------
#define NX (BB*NTOK*DMODEL)          // 16777216
#define NWQ (1536*512)               // 786432
#define NWO (512*512)                // 262144
#define NCONV (NX + NWQ + NWO)

__global__ __launch_bounds__(256) void conv_all(const float* __restrict__ X,
                                                const float* __restrict__ Wqkv,
                                                const float* __restrict__ Wout) {
    int idx = blockIdx.x * 256 + threadIdx.x;
    if (idx < NX) {
        int r = idx >> 9, k = idx & 511;
        int b = r >> 12, n = r & 4095;
        float v = X[(size_t)(b * NTOK + ((n + DISP) & 4095)) * DMODEL + k];
        g_xa[idx] = __float2half_rn(v);
    } else if (idx < NX + NWQ) {
        int i = idx - NX;
        int n = i >> 9, k = i & 511;
        g_wq[i] = __float2half_rn(Wqkv[(size_t)k * 1536 + n]);
    } else if (idx < NCONV) {
        int i = idx - NX - NWQ;
        int n = i >> 9, k = i & 511;
        g_wo[i] = __float2half_rn(Wout[(size_t)k * 512 + n]);
    }
}

// ---------------------------------------------------------------------------
// single-pass fp16 mma.sync GEMM (R9 config: KCH=64, scalar LDS fragments).
// Block tile 256x128, 8 warps (4x2) of 64x64.
// mode 0: Xr @ Wqkv -> q/k bf16 pair + v fp16, window layout
// mode 1: AO @ Wout (+bias) -> d_out with roll(+DISP)
// ---------------------------------------------------------------------------
#define KCH   64
#define TSTR  72
#define TILE_A_E (256*TSTR)
#define TILE_B_E (128*TSTR)
#define STAGE_E  (TILE_A_E + TILE_B_E)
#define GEMM_SMEM (2*STAGE_E*2)             // 110592 B

__global__ __launch_bounds__(256) void gemm256(const float* __restrict__ bias,
                                               float* __restrict__ Out, int mode) {
    extern __shared__ char smem_raw[];
    __half* smem = (__half*)smem_raw;
    const int tid = threadIdx.x;
    const int wid = tid >> 5;
    const int lid = tid & 31;
    const int row0 = blockIdx.y * 256;
    const int col0 = blockIdx.x * 128;
    const int wm = wid & 3, wn = wid >> 2;
    const int g = lid >> 2, cq = lid & 3;

    const __half* A  = mode ? g_ao : g_xa;
    const __half* Bw = mode ? g_wo : g_wq;

    auto issue = [&](int ko, int buf) {
        const int kbase = ko * KCH;
        __half* st = smem + buf * STAGE_E;
#pragma unroll
        for (int i = 0; i < 12; i++) {
            const int cidx = tid + i * 256;
            const __half* src;
            uint32_t dst;
            if (cidx < 2048) {
                const int r = cidx >> 3;
                const int c8 = cidx & 7;
                src = A + (size_t)(row0 + r) * 512 + kbase + c8 * 8;
                dst = smem_u32(st + r * TSTR + c8 * 8);
            } else {
                const int rem = cidx - 2048;
                const int r = rem >> 3;
                const int c8 = rem & 7;
                src = Bw + (size_t)(col0 + r) * 512 + kbase + c8 * 8;
                dst = smem_u32(st + TILE_A_E + r * TSTR + c8 * 8);
            }
            asm volatile("cp.async.cg.shared.global [%0], [%1], 16;"
                         :: "r"(dst), "l"(src));
        }
        asm volatile("cp.async.commit_group;");
    };

    float acc[4][8][4];
#pragma unroll
    for (int im = 0; im < 4; im++)
#pragma unroll
        for (int in_ = 0; in_ < 8; in_++)
#pragma unroll
            for (int e = 0; e < 4; e++) acc[im][in_][e] = 0.f;

    issue(0, 0);
    for (int ko = 0; ko < 8; ko++) {
        const int buf = ko & 1;
        if (ko + 1 < 8) {
            issue(ko + 1, buf ^ 1);
            asm volatile("cp.async.wait_group 1;");
        } else {
            asm volatile("cp.async.wait_group 0;");
        }
        __syncthreads();

        const __half* Ap = smem + buf * STAGE_E;
        const __half* Bp = Ap + TILE_A_E;

#pragma unroll
        for (int ks = 0; ks < 4; ks++) {
            const int kofs = ks * 16;
            uint32_t af[4][4];
#pragma unroll
            for (int im = 0; im < 4; im++) {
                const int rb = wm * 64 + im * 16 + g;
                af[im][0] = *(const uint32_t*)(Ap + rb * TSTR + kofs + cq * 2);
                af[im][1] = *(const uint32_t*)(Ap + (rb + 8) * TSTR + kofs + cq * 2);
                af[im][2] = *(const uint32_t*)(Ap + rb * TSTR + kofs + 8 + cq * 2);
                af[im][3] = *(const uint32_t*)(Ap + (rb + 8) * TSTR + kofs + 8 + cq * 2);
            }
#pragma unroll
            for (int in_ = 0; in_ < 8; in_++) {
                const int nr = wn * 64 + in_ * 8 + g;
                const uint32_t b0 = *(const uint32_t*)(Bp + nr * TSTR + kofs + cq * 2);
                const uint32_t b1 = *(const uint32_t*)(Bp + nr * TSTR + kofs + 8 + cq * 2);
#pragma unroll
                for (int im = 0; im < 4; im++)
                    mma16816h(acc[im][in_], af[im], b0, b1);
            }
        }
        __syncthreads();
    }

    // Epilogue
#pragma unroll
    for (int im = 0; im < 4; im++) {
#pragma unroll
        for (int in_ = 0; in_ < 8; in_++) {
            const int C0 = col0 + wn * 64 + in_ * 8 + cq * 2;
#pragma unroll
            for (int half = 0; half < 2; half++) {
                const int R = row0 + wm * 64 + im * 16 + g + half * 8;
                float vx = acc[im][in_][half * 2];
                float vy = acc[im][in_][half * 2 + 1];
                if (mode == 0) {
                    const int b2 = R >> 12, n2 = R & 4095;
                    const int w = n2 >> 5, jw = n2 & 31;
                    const int part = C0 >> 9;
                    const int h = (C0 & 511) >> 6;
                    const int dh = C0 & 63;
                    const size_t idx = (((size_t)((b2 * HH + h) * PP + jw)) * WW + w) * DH + dh;
                    if (part == 2) {
                        *(uint32_t*)(g_v + idx) = pack_h2(vx, vy);
                    } else {
                        uint32_t hi, lo;
                        pack_split(vx, vy, hi, lo);
                        __nv_bfloat16* d0 = (part == 0 ? g_q0 : g_k0);
                        __nv_bfloat16* d1 = (part == 0 ? g_q1 : g_k1);
                        *(uint32_t*)(d0 + idx) = hi;
                        *(uint32_t*)(d1 + idx) = lo;
                    }
                } else {
                    const int b2 = R >> 12, n2 = R & 4095;
                    const int dstn = (n2 + DISP) & 4095;
                    float2 v2;
                    v2.x = vx + __ldg(&bias[C0]);
                    v2.y = vy + __ldg(&bias[C0 + 1]);
                    *(float2*)(Out + (size_t)(b2 * NTOK + dstn) * DMODEL + C0) = v2;
                }
            }
        }
    }
}

// ---------------------------------------------------------------------------
// K2: tensor-core window attention (mask-split halves).
// QK: bf16 3-pass (error-critical). PV: fp16 single-pass.
// 5 smem tiles (q0,q1,k0,k1 bf16; v fp16) -> 93KB -> 2 CTAs/SM.
// ---------------------------------------------------------------------------
#define ATSTR 72
#define ATILE_E (WW*ATSTR)
#define ATILE_B (ATILE_E*2)
#define ATT_SMEM (1024 + 5*ATILE_B)          // 93184 B

__global__ __launch_bounds__(256) void attn_kernel(const float* __restrict__ pos_emb) {
    extern __shared__ char smem_raw[];
    float* slut = (float*)smem_raw;
    char* tiles = smem_raw + 1024;

    const int bid = blockIdx.x;
    const int tid = threadIdx.x;
    const int wid = tid >> 5;
    const int lid = tid & 31;
    const int g = lid >> 2, cq = lid & 3;

    if (tid < 2 * WW - 1) slut[tid] = pos_emb[tid];

    const size_t woff = (size_t)bid * (WW * DH);
    const char* srcs[5] = { (const char*)(g_q0 + woff), (const char*)(g_q1 + woff),
                            (const char*)(g_k0 + woff), (const char*)(g_k1 + woff),
                            (const char*)(g_v + woff) };
#pragma unroll
    for (int arr = 0; arr < 5; arr++) {
        const char* src = srcs[arr];
        char* tb = tiles + arr * ATILE_B;
#pragma unroll
        for (int ii = 0; ii < 4; ii++) {
            const int idx = ii * 256 + tid;       // 0..1023 16B chunks
            const int r = idx >> 3, c8 = idx & 7;
            const uint32_t dst = smem_u32(tb + (r * ATSTR + c8 * 8) * 2);
            asm volatile("cp.async.cg.shared.global [%0], [%1], 16;"
                         :: "r"(dst), "l"(src + (r * 64 + c8 * 8) * 2));
        }
    }
    asm volatile("cp.async.commit_group;");
    asm volatile("cp.async.wait_group 0;");
    __syncthreads();

    const uint32_t tiles0 = smem_u32(tiles);
    const uint32_t sq0B = tiles0;
    const uint32_t sq1B = tiles0 + ATILE_B;
    const uint32_t sk0B = tiles0 + 2 * ATILE_B;
    const uint32_t sk1B = tiles0 + 3 * ATILE_B;
    const uint32_t svB  = tiles0 + 4 * ATILE_B;

    const int half = wid >> 2;
    const int mrow = (wid & 3) * 16;
    const int qrow0 = half * 64 + mrow;
    const int kbase = half * 64;

    const int lrow = (lid & 7) + ((lid >> 3) & 1) * 8;
    const int lkad = (lid >> 4) * 8;
    const uint32_t qadd = (uint32_t)(((qrow0 + lrow) * ATSTR + lkad) * 2);
    const uint32_t kadd = (uint32_t)(((kbase + lrow) * ATSTR + lkad) * 2);
    const int vlrow = lid & 15;
    const int vcol = (lid >> 4) * 8;

    float S[8][4];
#pragma unroll
    for (int nt = 0; nt < 8; nt++)
#pragma unroll
        for (int e = 0; e < 4; e++) S[nt][e] = 0.f;

#pragma unroll
    for (int ks = 0; ks < 4; ks++) {
        const uint32_t kofsB = ks * 32;
        uint32_t aq0[4], aq1[4], kb0[4][4], kb1[4][4];
        ldsm_x4(aq0, sq0B + qadd + kofsB);
        ldsm_x4(aq1, sq1B + qadd + kofsB);
#pragma unroll
        for (int j = 0; j < 4; j++) {
            ldsm_x4(kb0[j], sk0B + kadd + j * (16 * ATSTR * 2) + kofsB);
            ldsm_x4(kb1[j], sk1B + kadd + j * (16 * ATSTR * 2) + kofsB);
        }
#pragma unroll
        for (int nt = 0; nt < 8; nt++) {
            const uint32_t b00 = kb0[nt >> 1][nt & 1];
            const uint32_t b01 = kb0[nt >> 1][2 + (nt & 1)];
            const uint32_t b10 = kb1[nt >> 1][nt & 1];
            const uint32_t b11 = kb1[nt >> 1][2 + (nt & 1)];
            mma16816(S[nt], aq0, b00, b01);
            mma16816(S[nt], aq0, b10, b11);
            mma16816(S[nt], aq1, b00, b01);
        }
    }

    const float scale = 0.125f;
    const int il0 = mrow + g;
    const int il1 = il0 + 8;
    float rs0 = 0.f, rs1 = 0.f;
#pragma unroll
    for (int nt = 0; nt < 8; nt++) {
        const int jl = nt * 8 + cq * 2;
        float p0 = __expf(S[nt][0] * scale + slut[jl - il0 + (WW - 1)]);
        float p1 = __expf(S[nt][1] * scale + slut[jl + 1 - il0 + (WW - 1)]);
        float p2 = __expf(S[nt][2] * scale + slut[jl - il1 + (WW - 1)]);
        float p3 = __expf(S[nt][3] * scale + slut[jl + 1 - il1 + (WW - 1)]);
        S[nt][0] = p0; S[nt][1] = p1; S[nt][2] = p2; S[nt][3] = p3;
        rs0 += p0 + p1;
        rs1 += p2 + p3;
    }
    rs0 += __shfl_xor_sync(0xFFFFFFFF, rs0, 1);
    rs0 += __shfl_xor_sync(0xFFFFFFFF, rs0, 2);
    rs1 += __shfl_xor_sync(0xFFFFFFFF, rs1, 1);
    rs1 += __shfl_xor_sync(0xFFFFFFFF, rs1, 2);
    const float inv0 = 1.0f / rs0;
    const float inv1 = 1.0f / rs1;

    // P fragments in fp16 (single pass)
    uint32_t pf[4][4];
#pragma unroll
    for (int ks = 0; ks < 4; ks++) {
        pf[ks][0] = pack_h2(S[2 * ks][0],     S[2 * ks][1]);
        pf[ks][1] = pack_h2(S[2 * ks][2],     S[2 * ks][3]);
        pf[ks][2] = pack_h2(S[2 * ks + 1][0], S[2 * ks + 1][1]);
        pf[ks][3] = pack_h2(S[2 * ks + 1][2], S[2 * ks + 1][3]);
    }

    float O[8][4];
#pragma unroll
    for (int nt = 0; nt < 8; nt++)
#pragma unroll
        for (int e = 0; e < 4; e++) O[nt][e] = 0.f;

#pragma unroll
    for (int ks = 0; ks < 4; ks++) {
        const int vrow16 = kbase + ks * 16 + vlrow;
#pragma unroll
        for (int j = 0; j < 4; j++) {
            uint32_t v0[4];
            const uint32_t vaddr = (uint32_t)((vrow16 * ATSTR + j * 16 + vcol) * 2);
            ldsm_x4t(v0, svB + vaddr);
            mma16816h(O[2 * j],     pf[ks], v0[0], v0[1]);
            mma16816h(O[2 * j + 1], pf[ks], v0[2], v0[3]);
        }
    }

    const int b  = bid >> 8;
    const int h  = (bid >> 5) & 7;
    const int jw = bid & 31;
    const int iw0 = half * 64 + il0;
    const int iw1 = half * 64 + il1;
    const size_t row0off = ((size_t)(b * NTOK + jw * WW + iw0)) * DMODEL + h * DH;
    const size_t row1off = ((size_t)(b * NTOK + jw * WW + iw1)) * DMODEL + h * DH;
#pragma unroll
    for (int nt = 0; nt < 8; nt++) {
        const int c = nt * 8 + cq * 2;
        *(uint32_t*)(g_ao + row0off + c) = pack_h2(O[nt][0] * inv0, O[nt][1] * inv0);
        *(uint32_t*)(g_ao + row1off + c) = pack_h2(O[nt][2] * inv1, O[nt][3] * inv1);
    }
}

// ---------------------------------------------------------------------------
extern "C" void kernel_launch(void* const* d_in, const int* in_sizes, int n_in,
                              void* d_out, int out_size) {
    const float* x       = (const float*)d_in[0];
    const float* Wqkv    = (const float*)d_in[1];
    const float* pos_emb = (const float*)d_in[2];
    const float* Wout    = (const float*)d_in[3];
    const float* bout    = (const float*)d_in[4];
    float* out = (float*)d_out;

    cudaFuncSetAttribute(gemm256, cudaFuncAttributeMaxDynamicSharedMemorySize, GEMM_SMEM);
    cudaFuncSetAttribute(attn_kernel, cudaFuncAttributeMaxDynamicSharedMemorySize, ATT_SMEM);

    conv_all<<<(NCONV + 255) / 256, 256>>>(x, Wqkv, Wout);

    // K1: QKV (M=32768 -> 128 row blocks, N=1536 -> 12 col blocks)
    gemm256<<<dim3(12, 128), 256, GEMM_SMEM>>>(nullptr, nullptr, 0);
    // K2: attention, one window per block
    attn_kernel<<<2048, 256, ATT_SMEM>>>(pos_emb);
    // K3: output projection (N=512 -> 4 col blocks) + bias + roll
    gemm256<<<dim3(4, 128), 256, GEMM_SMEM>>>(bout, out, 1);
}

// round 13
// speedup vs baseline: 1.2372x; 1.1316x over previous
#include <cuda_runtime.h>
#include <cuda_bf16.h>
#include <cuda_fp16.h>
#include <cstdint>

// Problem constants
#define BB   8
#define NTOK 4096
#define DMODEL 512
#define HH   8
#define DH   64
#define WW   128
#define PP   32
#define DISP 64

// ---------------------------------------------------------------------------
// Scratch (__device__ globals; allocation-free rule) — all fp16 now
// ---------------------------------------------------------------------------
__device__ __half g_q[BB*HH*PP*WW*DH];
__device__ __half g_k[BB*HH*PP*WW*DH];
__device__ __half g_v[BB*HH*PP*WW*DH];
__device__ __half g_xa[BB*NTOK*DMODEL];
__device__ __half g_wq[3*HH*DH*DMODEL];
__device__ __half g_wo[DMODEL*DMODEL];
__device__ __half g_ao[BB*NTOK*DMODEL];

__device__ __forceinline__ uint32_t smem_u32(const void* p) {
    uint32_t a;
    asm("{ .reg .u64 t; cvta.to.shared.u64 t, %1; cvt.u32.u64 %0, t; }"
        : "=r"(a) : "l"(p));
    return a;
}
__device__ __forceinline__ void mma16816h(float* d, const uint32_t* a,
                                          uint32_t b0, uint32_t b1) {
    asm volatile(
        "mma.sync.aligned.m16n8k16.row.col.f32.f16.f16.f32 "
        "{%0,%1,%2,%3}, {%4,%5,%6,%7}, {%8,%9}, {%0,%1,%2,%3};"
        : "+f"(d[0]), "+f"(d[1]), "+f"(d[2]), "+f"(d[3])
        : "r"(a[0]), "r"(a[1]), "r"(a[2]), "r"(a[3]), "r"(b0), "r"(b1));
}
__device__ __forceinline__ void ldsm_x4(uint32_t* r, uint32_t addr) {
    asm volatile("ldmatrix.sync.aligned.m8n8.x4.shared.b16 {%0,%1,%2,%3}, [%4];"
                 : "=r"(r[0]), "=r"(r[1]), "=r"(r[2]), "=r"(r[3]) : "r"(addr));
}
__device__ __forceinline__ void ldsm_x4t(uint32_t* r, uint32_t addr) {
    asm volatile("ldmatrix.sync.aligned.m8n8.x4.trans.shared.b16 {%0,%1,%2,%3}, [%4];"
                 : "=r"(r[0]), "=r"(r[1]), "=r"(r[2]), "=r"(r[3]) : "r"(addr));
}
__device__ __forceinline__ uint32_t pack_h2(float x, float y) {
    __half2 h; h.x = __float2half_rn(x); h.y = __float2half_rn(y);
    return *(uint32_t*)&h;
}

// ---------------------------------------------------------------------------
// Fused prepass: X roll+fp16, Wqkv^T fp16, Wout^T fp16 (one linear dispatch)
// ---------------------------------------------------------------------------
#define NX (BB*NTOK*DMODEL)
#define NWQ (1536*512)
#define NWO (512*512)
#define NCONV (NX + NWQ + NWO)

__global__ __launch_bounds__(256) void conv_all(const float* __restrict__ X,
                                                const float* __restrict__ Wqkv,
                                                const float* __restrict__ Wout) {
    int idx = blockIdx.x * 256 + threadIdx.x;
    if (idx < NX) {
        int r = idx >> 9, k = idx & 511;
        int b = r >> 12, n = r & 4095;
        float v = X[(size_t)(b * NTOK + ((n + DISP) & 4095)) * DMODEL + k];
        g_xa[idx] = __float2half_rn(v);
    } else if (idx < NX + NWQ) {
        int i = idx - NX;
        int n = i >> 9, k = i & 511;
        g_wq[i] = __float2half_rn(Wqkv[(size_t)k * 1536 + n]);
    } else if (idx < NCONV) {
        int i = idx - NX - NWQ;
        int n = i >> 9, k = i & 511;
        g_wo[i] = __float2half_rn(Wout[(size_t)k * 512 + n]);
    }
}

// ---------------------------------------------------------------------------
// single-pass fp16 mma.sync GEMM. Block tile 256x128, 8 warps (4x2) of 64x64.
// K=512 in 8 chunks of 64, 2-stage cp.async, scalar LDS fragments.
// mode 0: Xr @ Wqkv -> q/k/v fp16 window layout
// mode 1: AO @ Wout (+bias) -> d_out with roll(+DISP)
// ---------------------------------------------------------------------------
#define KCH   64
#define TSTR  72
#define TILE_A_E (256*TSTR)
#define TILE_B_E (128*TSTR)
#define STAGE_E  (TILE_A_E + TILE_B_E)
#define GEMM_SMEM (2*STAGE_E*2)             // 110592 B

__global__ __launch_bounds__(256) void gemm256(const float* __restrict__ bias,
                                               float* __restrict__ Out, int mode) {
    extern __shared__ char smem_raw[];
    __half* smem = (__half*)smem_raw;
    const int tid = threadIdx.x;
    const int wid = tid >> 5;
    const int lid = tid & 31;
    const int row0 = blockIdx.y * 256;
    const int col0 = blockIdx.x * 128;
    const int wm = wid & 3, wn = wid >> 2;
    const int g = lid >> 2, cq = lid & 3;

    const __half* A  = mode ? g_ao : g_xa;
    const __half* Bw = mode ? g_wo : g_wq;

    auto issue = [&](int ko, int buf) {
        const int kbase = ko * KCH;
        __half* st = smem + buf * STAGE_E;
#pragma unroll
        for (int i = 0; i < 12; i++) {
            const int cidx = tid + i * 256;
            const __half* src;
            uint32_t dst;
            if (cidx < 2048) {
                const int r = cidx >> 3;
                const int c8 = cidx & 7;
                src = A + (size_t)(row0 + r) * 512 + kbase + c8 * 8;
                dst = smem_u32(st + r * TSTR + c8 * 8);
            } else {
                const int rem = cidx - 2048;
                const int r = rem >> 3;
                const int c8 = rem & 7;
                src = Bw + (size_t)(col0 + r) * 512 + kbase + c8 * 8;
                dst = smem_u32(st + TILE_A_E + r * TSTR + c8 * 8);
            }
            asm volatile("cp.async.cg.shared.global [%0], [%1], 16;"
                         :: "r"(dst), "l"(src));
        }
        asm volatile("cp.async.commit_group;");
    };

    float acc[4][8][4];
#pragma unroll
    for (int im = 0; im < 4; im++)
#pragma unroll
        for (int in_ = 0; in_ < 8; in_++)
#pragma unroll
            for (int e = 0; e < 4; e++) acc[im][in_][e] = 0.f;

    issue(0, 0);
    for (int ko = 0; ko < 8; ko++) {
        const int buf = ko & 1;
        if (ko + 1 < 8) {
            issue(ko + 1, buf ^ 1);
            asm volatile("cp.async.wait_group 1;");
        } else {
            asm volatile("cp.async.wait_group 0;");
        }
        __syncthreads();

        const __half* Ap = smem + buf * STAGE_E;
        const __half* Bp = Ap + TILE_A_E;

#pragma unroll
        for (int ks = 0; ks < 4; ks++) {
            const int kofs = ks * 16;
            uint32_t af[4][4];
#pragma unroll
            for (int im = 0; im < 4; im++) {
                const int rb = wm * 64 + im * 16 + g;
                af[im][0] = *(const uint32_t*)(Ap + rb * TSTR + kofs + cq * 2);
                af[im][1] = *(const uint32_t*)(Ap + (rb + 8) * TSTR + kofs + cq * 2);
                af[im][2] = *(const uint32_t*)(Ap + rb * TSTR + kofs + 8 + cq * 2);
                af[im][3] = *(const uint32_t*)(Ap + (rb + 8) * TSTR + kofs + 8 + cq * 2);
            }
#pragma unroll
            for (int in_ = 0; in_ < 8; in_++) {
                const int nr = wn * 64 + in_ * 8 + g;
                const uint32_t b0 = *(const uint32_t*)(Bp + nr * TSTR + kofs + cq * 2);
                const uint32_t b1 = *(const uint32_t*)(Bp + nr * TSTR + kofs + 8 + cq * 2);
#pragma unroll
                for (int im = 0; im < 4; im++)
                    mma16816h(acc[im][in_], af[im], b0, b1);
            }
        }
        __syncthreads();
    }

    // Epilogue
#pragma unroll
    for (int im = 0; im < 4; im++) {
#pragma unroll
        for (int in_ = 0; in_ < 8; in_++) {
            const int C0 = col0 + wn * 64 + in_ * 8 + cq * 2;
#pragma unroll
            for (int half = 0; half < 2; half++) {
                const int R = row0 + wm * 64 + im * 16 + g + half * 8;
                float vx = acc[im][in_][half * 2];
                float vy = acc[im][in_][half * 2 + 1];
                if (mode == 0) {
                    const int b2 = R >> 12, n2 = R & 4095;
                    const int w = n2 >> 5, jw = n2 & 31;
                    const int part = C0 >> 9;
                    const int h = (C0 & 511) >> 6;
                    const int dh = C0 & 63;
                    const size_t idx = (((size_t)((b2 * HH + h) * PP + jw)) * WW + w) * DH + dh;
                    __half* dst = (part == 0 ? g_q : part == 1 ? g_k : g_v);
                    *(uint32_t*)(dst + idx) = pack_h2(vx, vy);
                } else {
                    const int b2 = R >> 12, n2 = R & 4095;
                    const int dstn = (n2 + DISP) & 4095;
                    float2 v2;
                    v2.x = vx + __ldg(&bias[C0]);
                    v2.y = vy + __ldg(&bias[C0 + 1]);
                    *(float2*)(Out + (size_t)(b2 * NTOK + dstn) * DMODEL + C0) = v2;
                }
            }
        }
    }
}

// ---------------------------------------------------------------------------
// K2: tensor-core window attention (mask-split halves), all fp16 single-pass.
// 3 smem tiles (q,k,v fp16) = 55KB -> high occupancy.
// ---------------------------------------------------------------------------
#define ATSTR 72
#define ATILE_E (WW*ATSTR)
#define ATILE_B (ATILE_E*2)
#define ATT_SMEM (1024 + 3*ATILE_B)          // 56320 B

__global__ __launch_bounds__(256) void attn_kernel(const float* __restrict__ pos_emb) {
    extern __shared__ char smem_raw[];
    float* slut = (float*)smem_raw;
    char* tiles = smem_raw + 1024;

    const int bid = blockIdx.x;
    const int tid = threadIdx.x;
    const int wid = tid >> 5;
    const int lid = tid & 31;
    const int g = lid >> 2, cq = lid & 3;

    if (tid < 2 * WW - 1) slut[tid] = pos_emb[tid];

    const size_t woff = (size_t)bid * (WW * DH);
    const char* srcs[3] = { (const char*)(g_q + woff), (const char*)(g_k + woff),
                            (const char*)(g_v + woff) };
#pragma unroll
    for (int arr = 0; arr < 3; arr++) {
        const char* src = srcs[arr];
        char* tb = tiles + arr * ATILE_B;
#pragma unroll
        for (int ii = 0; ii < 4; ii++) {
            const int idx = ii * 256 + tid;       // 0..1023 16B chunks
            const int r = idx >> 3, c8 = idx & 7;
            const uint32_t dst = smem_u32(tb + (r * ATSTR + c8 * 8) * 2);
            asm volatile("cp.async.cg.shared.global [%0], [%1], 16;"
                         :: "r"(dst), "l"(src + (r * 64 + c8 * 8) * 2));
        }
    }
    asm volatile("cp.async.commit_group;");
    asm volatile("cp.async.wait_group 0;");
    __syncthreads();

    const uint32_t tiles0 = smem_u32(tiles);
    const uint32_t sqB = tiles0;
    const uint32_t skB = tiles0 + ATILE_B;
    const uint32_t svB = tiles0 + 2 * ATILE_B;

    const int half = wid >> 2;
    const int mrow = (wid & 3) * 16;
    const int qrow0 = half * 64 + mrow;
    const int kbase = half * 64;

    const int lrow = (lid & 7) + ((lid >> 3) & 1) * 8;
    const int lkad = (lid >> 4) * 8;
    const uint32_t qadd = (uint32_t)(((qrow0 + lrow) * ATSTR + lkad) * 2);
    const uint32_t kadd = (uint32_t)(((kbase + lrow) * ATSTR + lkad) * 2);
    const int vlrow = lid & 15;
    const int vcol = (lid >> 4) * 8;

    float S[8][4];
#pragma unroll
    for (int nt = 0; nt < 8; nt++)
#pragma unroll
        for (int e = 0; e < 4; e++) S[nt][e] = 0.f;

#pragma unroll
    for (int ks = 0; ks < 4; ks++) {
        const uint32_t kofsB = ks * 32;
        uint32_t aq[4], kb[4][4];
        ldsm_x4(aq, sqB + qadd + kofsB);
#pragma unroll
        for (int j = 0; j < 4; j++)
            ldsm_x4(kb[j], skB + kadd + j * (16 * ATSTR * 2) + kofsB);
#pragma unroll
        for (int nt = 0; nt < 8; nt++) {
            const uint32_t b0 = kb[nt >> 1][nt & 1];
            const uint32_t b1 = kb[nt >> 1][2 + (nt & 1)];
            mma16816h(S[nt], aq, b0, b1);
        }
    }

    const float scale = 0.125f;
    const int il0 = mrow + g;
    const int il1 = il0 + 8;
    float rs0 = 0.f, rs1 = 0.f;
#pragma unroll
    for (int nt = 0; nt < 8; nt++) {
        const int jl = nt * 8 + cq * 2;
        float p0 = __expf(S[nt][0] * scale + slut[jl - il0 + (WW - 1)]);
        float p1 = __expf(S[nt][1] * scale + slut[jl + 1 - il0 + (WW - 1)]);
        float p2 = __expf(S[nt][2] * scale + slut[jl - il1 + (WW - 1)]);
        float p3 = __expf(S[nt][3] * scale + slut[jl + 1 - il1 + (WW - 1)]);
        S[nt][0] = p0; S[nt][1] = p1; S[nt][2] = p2; S[nt][3] = p3;
        rs0 += p0 + p1;
        rs1 += p2 + p3;
    }
    rs0 += __shfl_xor_sync(0xFFFFFFFF, rs0, 1);
    rs0 += __shfl_xor_sync(0xFFFFFFFF, rs0, 2);
    rs1 += __shfl_xor_sync(0xFFFFFFFF, rs1, 1);
    rs1 += __shfl_xor_sync(0xFFFFFFFF, rs1, 2);
    const float inv0 = 1.0f / rs0;
    const float inv1 = 1.0f / rs1;

    // P fragments in fp16 (single pass)
    uint32_t pf[4][4];
#pragma unroll
    for (int ks = 0; ks < 4; ks++) {
        pf[ks][0] = pack_h2(S[2 * ks][0],     S[2 * ks][1]);
        pf[ks][1] = pack_h2(S[2 * ks][2],     S[2 * ks][3]);
        pf[ks][2] = pack_h2(S[2 * ks + 1][0], S[2 * ks + 1][1]);
        pf[ks][3] = pack_h2(S[2 * ks + 1][2], S[2 * ks + 1][3]);
    }

    float O[8][4];
#pragma unroll
    for (int nt = 0; nt < 8; nt++)
#pragma unroll
        for (int e = 0; e < 4; e++) O[nt][e] = 0.f;

#pragma unroll
    for (int ks = 0; ks < 4; ks++) {
        const int vrow16 = kbase + ks * 16 + vlrow;
#pragma unroll
        for (int j = 0; j < 4; j++) {
            uint32_t v0[4];
            const uint32_t vaddr = (uint32_t)((vrow16 * ATSTR + j * 16 + vcol) * 2);
            ldsm_x4t(v0, svB + vaddr);
            mma16816h(O[2 * j],     pf[ks], v0[0], v0[1]);
            mma16816h(O[2 * j + 1], pf[ks], v0[2], v0[3]);
        }
    }

    const int b  = bid >> 8;
    const int h  = (bid >> 5) & 7;
    const int jw = bid & 31;
    const int iw0 = half * 64 + il0;
    const int iw1 = half * 64 + il1;
    const size_t row0off = ((size_t)(b * NTOK + jw * WW + iw0)) * DMODEL + h * DH;
    const size_t row1off = ((size_t)(b * NTOK + jw * WW + iw1)) * DMODEL + h * DH;
#pragma unroll
    for (int nt = 0; nt < 8; nt++) {
        const int c = nt * 8 + cq * 2;
        *(uint32_t*)(g_ao + row0off + c) = pack_h2(O[nt][0] * inv0, O[nt][1] * inv0);
        *(uint32_t*)(g_ao + row1off + c) = pack_h2(O[nt][2] * inv1, O[nt][3] * inv1);
    }
}

// ---------------------------------------------------------------------------
extern "C" void kernel_launch(void* const* d_in, const int* in_sizes, int n_in,
                              void* d_out, int out_size) {
    const float* x       = (const float*)d_in[0];
    const float* Wqkv    = (const float*)d_in[1];
    const float* pos_emb = (const float*)d_in[2];
    const float* Wout    = (const float*)d_in[3];
    const float* bout    = (const float*)d_in[4];
    float* out = (float*)d_out;

    cudaFuncSetAttribute(gemm256, cudaFuncAttributeMaxDynamicSharedMemorySize, GEMM_SMEM);
    cudaFuncSetAttribute(attn_kernel, cudaFuncAttributeMaxDynamicSharedMemorySize, ATT_SMEM);

    conv_all<<<(NCONV + 255) / 256, 256>>>(x, Wqkv, Wout);

    // K1: QKV (M=32768 -> 128 row blocks, N=1536 -> 12 col blocks)
    gemm256<<<dim3(12, 128), 256, GEMM_SMEM>>>(nullptr, nullptr, 0);
    // K2: attention, one window per block
    attn_kernel<<<2048, 256, ATT_SMEM>>>(pos_emb);
    // K3: output projection (N=512 -> 4 col blocks) + bias + roll
    gemm256<<<dim3(4, 128), 256, GEMM_SMEM>>>(bout, out, 1);
}

// round 14
// speedup vs baseline: 1.3420x; 1.0847x over previous
#include <cuda_runtime.h>
#include <cuda_bf16.h>
#include <cuda_fp16.h>
#include <cstdint>

// Problem constants
#define BB   8
#define NTOK 4096
#define DMODEL 512
#define HH   8
#define DH   64
#define WW   128
#define PP   32
#define DISP 64

// ---------------------------------------------------------------------------
// Scratch (__device__ globals; allocation-free rule) — all fp16
// ---------------------------------------------------------------------------
__device__ __half g_q[BB*HH*PP*WW*DH];
__device__ __half g_k[BB*HH*PP*WW*DH];
__device__ __half g_v[BB*HH*PP*WW*DH];
__device__ __half g_xa[BB*NTOK*DMODEL];
__device__ __half g_wq[3*HH*DH*DMODEL];
__device__ __half g_wo[DMODEL*DMODEL];
__device__ __half g_ao[BB*NTOK*DMODEL];

__device__ __forceinline__ uint32_t smem_u32(const void* p) {
    uint32_t a;
    asm("{ .reg .u64 t; cvta.to.shared.u64 t, %1; cvt.u32.u64 %0, t; }"
        : "=r"(a) : "l"(p));
    return a;
}
__device__ __forceinline__ void mma16816h(float* d, const uint32_t* a,
                                          uint32_t b0, uint32_t b1) {
    asm volatile(
        "mma.sync.aligned.m16n8k16.row.col.f32.f16.f16.f32 "
        "{%0,%1,%2,%3}, {%4,%5,%6,%7}, {%8,%9}, {%0,%1,%2,%3};"
        : "+f"(d[0]), "+f"(d[1]), "+f"(d[2]), "+f"(d[3])
        : "r"(a[0]), "r"(a[1]), "r"(a[2]), "r"(a[3]), "r"(b0), "r"(b1));
}
__device__ __forceinline__ void ldsm_x4(uint32_t* r, uint32_t addr) {
    asm volatile("ldmatrix.sync.aligned.m8n8.x4.shared.b16 {%0,%1,%2,%3}, [%4];"
                 : "=r"(r[0]), "=r"(r[1]), "=r"(r[2]), "=r"(r[3]) : "r"(addr));
}
__device__ __forceinline__ void ldsm_x4t(uint32_t* r, uint32_t addr) {
    asm volatile("ldmatrix.sync.aligned.m8n8.x4.trans.shared.b16 {%0,%1,%2,%3}, [%4];"
                 : "=r"(r[0]), "=r"(r[1]), "=r"(r[2]), "=r"(r[3]) : "r"(addr));
}
__device__ __forceinline__ uint32_t pack_h2(float x, float y) {
    __half2 h; h.x = __float2half_rn(x); h.y = __float2half_rn(y);
    return *(uint32_t*)&h;
}

// ---------------------------------------------------------------------------
// Fused prepass (x4 vectorized): X roll+fp16, Wqkv^T fp16, Wout^T fp16
// ---------------------------------------------------------------------------
#define NX (BB*NTOK*DMODEL)
#define NWQ (1536*512)
#define NWO (512*512)
#define NCONV4 ((NX + NWQ + NWO) / 4)

__global__ __launch_bounds__(256) void conv_all(const float* __restrict__ X,
                                                const float* __restrict__ Wqkv,
                                                const float* __restrict__ Wout) {
    int q = blockIdx.x * 256 + threadIdx.x;
    if (q >= NCONV4) return;
    int idx = q * 4;
    float4 v;
    __half* dst;
    if (idx < NX) {
        int r = idx >> 9, k = idx & 511;
        int b = r >> 12, n = r & 4095;
        v = *(const float4*)(X + (size_t)(b * NTOK + ((n + DISP) & 4095)) * DMODEL + k);
        dst = g_xa + idx;
    } else if (idx < NX + NWQ) {
        int i = idx - NX;
        int n = i >> 9, k = i & 511;   // 4 consecutive k, same n — strided gather
        const float* s = Wqkv + (size_t)k * 1536 + n;
        v.x = s[0]; v.y = s[1536]; v.z = s[2 * 1536]; v.w = s[3 * 1536];
        dst = g_wq + i;
    } else {
        int i = idx - NX - NWQ;
        int n = i >> 9, k = i & 511;
        const float* s = Wout + (size_t)k * 512 + n;
        v.x = s[0]; v.y = s[512]; v.z = s[2 * 512]; v.w = s[3 * 512];
        dst = g_wo + i;
    }
    uint2 o;
    o.x = pack_h2(v.x, v.y);
    o.y = pack_h2(v.z, v.w);
    *(uint2*)dst = o;
}

// ---------------------------------------------------------------------------
// single-pass fp16 mma.sync GEMM. Block tile 256x128, 8 warps (4x2) of 64x64.
// K=512 in 8 chunks of 64. 3-stage cp.async pipeline, ONE sync per chunk.
// mode 0: Xr @ Wqkv -> q/k/v fp16 window layout
// mode 1: AO @ Wout (+bias) -> d_out with roll(+DISP)
// ---------------------------------------------------------------------------
#define KCH   64
#define TSTR  72
#define TILE_A_E (256*TSTR)
#define TILE_B_E (128*TSTR)
#define STAGE_E  (TILE_A_E + TILE_B_E)
#define NSTAGE 3
#define GEMM_SMEM (NSTAGE*STAGE_E*2)        // 165888 B

__global__ __launch_bounds__(256) void gemm256(const float* __restrict__ bias,
                                               float* __restrict__ Out, int mode) {
    extern __shared__ char smem_raw[];
    __half* smem = (__half*)smem_raw;
    const int tid = threadIdx.x;
    const int wid = tid >> 5;
    const int lid = tid & 31;
    const int row0 = blockIdx.y * 256;
    const int col0 = blockIdx.x * 128;
    const int wm = wid & 3, wn = wid >> 2;
    const int g = lid >> 2, cq = lid & 3;

    const __half* A  = mode ? g_ao : g_xa;
    const __half* Bw = mode ? g_wo : g_wq;

    auto issue = [&](int ko) {
        const int kbase = ko * KCH;
        __half* st = smem + (ko % NSTAGE) * STAGE_E;
#pragma unroll
        for (int i = 0; i < 12; i++) {
            const int cidx = tid + i * 256;
            const __half* src;
            uint32_t dst;
            if (cidx < 2048) {
                const int r = cidx >> 3;
                const int c8 = cidx & 7;
                src = A + (size_t)(row0 + r) * 512 + kbase + c8 * 8;
                dst = smem_u32(st + r * TSTR + c8 * 8);
            } else {
                const int rem = cidx - 2048;
                const int r = rem >> 3;
                const int c8 = rem & 7;
                src = Bw + (size_t)(col0 + r) * 512 + kbase + c8 * 8;
                dst = smem_u32(st + TILE_A_E + r * TSTR + c8 * 8);
            }
            asm volatile("cp.async.cg.shared.global [%0], [%1], 16;"
                         :: "r"(dst), "l"(src));
        }
        asm volatile("cp.async.commit_group;");
    };

    float acc[4][8][4];
#pragma unroll
    for (int im = 0; im < 4; im++)
#pragma unroll
        for (int in_ = 0; in_ < 8; in_++)
#pragma unroll
            for (int e = 0; e < 4; e++) acc[im][in_][e] = 0.f;

    issue(0);
    issue(1);
    for (int ko = 0; ko < 8; ko++) {
        // wait for chunk ko (allow the one younger group to stay pending)
        if (ko + 1 < 8) {
            asm volatile("cp.async.wait_group 1;");
        } else {
            asm volatile("cp.async.wait_group 0;");
        }
        __syncthreads();
        // safe to issue ko+2 into buffer (ko+2)%3=(ko-1)%3: all warps finished
        // reading it (compute(ko-1)) before arriving at the sync above.
        if (ko + 2 < 8) issue(ko + 2);

        const __half* Ap = smem + (ko % NSTAGE) * STAGE_E;
        const __half* Bp = Ap + TILE_A_E;

#pragma unroll
        for (int ks = 0; ks < 4; ks++) {
            const int kofs = ks * 16;
            uint32_t af[4][4];
#pragma unroll
            for (int im = 0; im < 4; im++) {
                const int rb = wm * 64 + im * 16 + g;
                af[im][0] = *(const uint32_t*)(Ap + rb * TSTR + kofs + cq * 2);
                af[im][1] = *(const uint32_t*)(Ap + (rb + 8) * TSTR + kofs + cq * 2);
                af[im][2] = *(const uint32_t*)(Ap + rb * TSTR + kofs + 8 + cq * 2);
                af[im][3] = *(const uint32_t*)(Ap + (rb + 8) * TSTR + kofs + 8 + cq * 2);
            }
#pragma unroll
            for (int in_ = 0; in_ < 8; in_++) {
                const int nr = wn * 64 + in_ * 8 + g;
                const uint32_t b0 = *(const uint32_t*)(Bp + nr * TSTR + kofs + cq * 2);
                const uint32_t b1 = *(const uint32_t*)(Bp + nr * TSTR + kofs + 8 + cq * 2);
#pragma unroll
                for (int im = 0; im < 4; im++)
                    mma16816h(acc[im][in_], af[im], b0, b1);
            }
        }
    }

    // Epilogue
#pragma unroll
    for (int im = 0; im < 4; im++) {
#pragma unroll
        for (int in_ = 0; in_ < 8; in_++) {
            const int C0 = col0 + wn * 64 + in_ * 8 + cq * 2;
#pragma unroll
            for (int half = 0; half < 2; half++) {
                const int R = row0 + wm * 64 + im * 16 + g + half * 8;
                float vx = acc[im][in_][half * 2];
                float vy = acc[im][in_][half * 2 + 1];
                if (mode == 0) {
                    const int b2 = R >> 12, n2 = R & 4095;
                    const int w = n2 >> 5, jw = n2 & 31;
                    const int part = C0 >> 9;
                    const int h = (C0 & 511) >> 6;
                    const int dh = C0 & 63;
                    const size_t idx = (((size_t)((b2 * HH + h) * PP + jw)) * WW + w) * DH + dh;
                    __half* dst = (part == 0 ? g_q : part == 1 ? g_k : g_v);
                    *(uint32_t*)(dst + idx) = pack_h2(vx, vy);
                } else {
                    const int b2 = R >> 12, n2 = R & 4095;
                    const int dstn = (n2 + DISP) & 4095;
                    float2 v2;
                    v2.x = vx + __ldg(&bias[C0]);
                    v2.y = vy + __ldg(&bias[C0 + 1]);
                    *(float2*)(Out + (size_t)(b2 * NTOK + dstn) * DMODEL + C0) = v2;
                }
            }
        }
    }
}

// ---------------------------------------------------------------------------
// K2: tensor-core window attention (mask-split halves), all fp16 single-pass.
// ---------------------------------------------------------------------------
#define ATSTR 72
#define ATILE_E (WW*ATSTR)
#define ATILE_B (ATILE_E*2)
#define ATT_SMEM (1024 + 3*ATILE_B)          // 56320 B

__global__ __launch_bounds__(256) void attn_kernel(const float* __restrict__ pos_emb) {
    extern __shared__ char smem_raw[];
    float* slut = (float*)smem_raw;
    char* tiles = smem_raw + 1024;

    const int bid = blockIdx.x;
    const int tid = threadIdx.x;
    const int wid = tid >> 5;
    const int lid = tid & 31;
    const int g = lid >> 2, cq = lid & 3;

    if (tid < 2 * WW - 1) slut[tid] = pos_emb[tid];

    const size_t woff = (size_t)bid * (WW * DH);
    const char* srcs[3] = { (const char*)(g_q + woff), (const char*)(g_k + woff),
                            (const char*)(g_v + woff) };
#pragma unroll
    for (int arr = 0; arr < 3; arr++) {
        const char* src = srcs[arr];
        char* tb = tiles + arr * ATILE_B;
#pragma unroll
        for (int ii = 0; ii < 4; ii++) {
            const int idx = ii * 256 + tid;
            const int r = idx >> 3, c8 = idx & 7;
            const uint32_t dst = smem_u32(tb + (r * ATSTR + c8 * 8) * 2);
            asm volatile("cp.async.cg.shared.global [%0], [%1], 16;"
                         :: "r"(dst), "l"(src + (r * 64 + c8 * 8) * 2));
        }
    }
    asm volatile("cp.async.commit_group;");
    asm volatile("cp.async.wait_group 0;");
    __syncthreads();

    const uint32_t tiles0 = smem_u32(tiles);
    const uint32_t sqB = tiles0;
    const uint32_t skB = tiles0 + ATILE_B;
    const uint32_t svB = tiles0 + 2 * ATILE_B;

    const int half = wid >> 2;
    const int mrow = (wid & 3) * 16;
    const int qrow0 = half * 64 + mrow;
    const int kbase = half * 64;

    const int lrow = (lid & 7) + ((lid >> 3) & 1) * 8;
    const int lkad = (lid >> 4) * 8;
    const uint32_t qadd = (uint32_t)(((qrow0 + lrow) * ATSTR + lkad) * 2);
    const uint32_t kadd = (uint32_t)(((kbase + lrow) * ATSTR + lkad) * 2);
    const int vlrow = lid & 15;
    const int vcol = (lid >> 4) * 8;

    float S[8][4];
#pragma unroll
    for (int nt = 0; nt < 8; nt++)
#pragma unroll
        for (int e = 0; e < 4; e++) S[nt][e] = 0.f;

#pragma unroll
    for (int ks = 0; ks < 4; ks++) {
        const uint32_t kofsB = ks * 32;
        uint32_t aq[4], kb[4][4];
        ldsm_x4(aq, sqB + qadd + kofsB);
#pragma unroll
        for (int j = 0; j < 4; j++)
            ldsm_x4(kb[j], skB + kadd + j * (16 * ATSTR * 2) + kofsB);
#pragma unroll
        for (int nt = 0; nt < 8; nt++) {
            const uint32_t b0 = kb[nt >> 1][nt & 1];
            const uint32_t b1 = kb[nt >> 1][2 + (nt & 1)];
            mma16816h(S[nt], aq, b0, b1);
        }
    }

    const float scale = 0.125f;
    const int il0 = mrow + g;
    const int il1 = il0 + 8;
    float rs0 = 0.f, rs1 = 0.f;
#pragma unroll
    for (int nt = 0; nt < 8; nt++) {
        const int jl = nt * 8 + cq * 2;
        float p0 = __expf(S[nt][0] * scale + slut[jl - il0 + (WW - 1)]);
        float p1 = __expf(S[nt][1] * scale + slut[jl + 1 - il0 + (WW - 1)]);
        float p2 = __expf(S[nt][2] * scale + slut[jl - il1 + (WW - 1)]);
        float p3 = __expf(S[nt][3] * scale + slut[jl + 1 - il1 + (WW - 1)]);
        S[nt][0] = p0; S[nt][1] = p1; S[nt][2] = p2; S[nt][3] = p3;
        rs0 += p0 + p1;
        rs1 += p2 + p3;
    }
    rs0 += __shfl_xor_sync(0xFFFFFFFF, rs0, 1);
    rs0 += __shfl_xor_sync(0xFFFFFFFF, rs0, 2);
    rs1 += __shfl_xor_sync(0xFFFFFFFF, rs1, 1);
    rs1 += __shfl_xor_sync(0xFFFFFFFF, rs1, 2);
    const float inv0 = 1.0f / rs0;
    const float inv1 = 1.0f / rs1;

    uint32_t pf[4][4];
#pragma unroll
    for (int ks = 0; ks < 4; ks++) {
        pf[ks][0] = pack_h2(S[2 * ks][0],     S[2 * ks][1]);
        pf[ks][1] = pack_h2(S[2 * ks][2],     S[2 * ks][3]);
        pf[ks][2] = pack_h2(S[2 * ks + 1][0], S[2 * ks + 1][1]);
        pf[ks][3] = pack_h2(S[2 * ks + 1][2], S[2 * ks + 1][3]);
    }

    float O[8][4];
#pragma unroll
    for (int nt = 0; nt < 8; nt++)
#pragma unroll
        for (int e = 0; e < 4; e++) O[nt][e] = 0.f;

#pragma unroll
    for (int ks = 0; ks < 4; ks++) {
        const int vrow16 = kbase + ks * 16 + vlrow;
#pragma unroll
        for (int j = 0; j < 4; j++) {
            uint32_t v0[4];
            const uint32_t vaddr = (uint32_t)((vrow16 * ATSTR + j * 16 + vcol) * 2);
            ldsm_x4t(v0, svB + vaddr);
            mma16816h(O[2 * j],     pf[ks], v0[0], v0[1]);
            mma16816h(O[2 * j + 1], pf[ks], v0[2], v0[3]);
        }
    }

    const int b  = bid >> 8;
    const int h  = (bid >> 5) & 7;
    const int jw = bid & 31;
    const int iw0 = half * 64 + il0;
    const int iw1 = half * 64 + il1;
    const size_t row0off = ((size_t)(b * NTOK + jw * WW + iw0)) * DMODEL + h * DH;
    const size_t row1off = ((size_t)(b * NTOK + jw * WW + iw1)) * DMODEL + h * DH;
#pragma unroll
    for (int nt = 0; nt < 8; nt++) {
        const int c = nt * 8 + cq * 2;
        *(uint32_t*)(g_ao + row0off + c) = pack_h2(O[nt][0] * inv0, O[nt][1] * inv0);
        *(uint32_t*)(g_ao + row1off + c) = pack_h2(O[nt][2] * inv1, O[nt][3] * inv1);
    }
}

// ---------------------------------------------------------------------------
extern "C" void kernel_launch(void* const* d_in, const int* in_sizes, int n_in,
                              void* d_out, int out_size) {
    const float* x       = (const float*)d_in[0];
    const float* Wqkv    = (const float*)d_in[1];
    const float* pos_emb = (const float*)d_in[2];
    const float* Wout    = (const float*)d_in[3];
    const float* bout    = (const float*)d_in[4];
    float* out = (float*)d_out;

    cudaFuncSetAttribute(gemm256, cudaFuncAttributeMaxDynamicSharedMemorySize, GEMM_SMEM);
    cudaFuncSetAttribute(attn_kernel, cudaFuncAttributeMaxDynamicSharedMemorySize, ATT_SMEM);

    conv_all<<<(NCONV4 + 255) / 256, 256>>>(x, Wqkv, Wout);

    // K1: QKV (M=32768 -> 128 row blocks, N=1536 -> 12 col blocks)
    gemm256<<<dim3(12, 128), 256, GEMM_SMEM>>>(nullptr, nullptr, 0);
    // K2: attention, one window per block
    attn_kernel<<<2048, 256, ATT_SMEM>>>(pos_emb);
    // K3: output projection (N=512 -> 4 col blocks) + bias + roll
    gemm256<<<dim3(4, 128), 256, GEMM_SMEM>>>(bout, out, 1);
}

// round 15
// speedup vs baseline: 1.4852x; 1.1067x over previous
#include <cuda_runtime.h>
#include <cuda_bf16.h>
#include <cuda_fp16.h>
#include <cstdint>

// Problem constants
#define BB   8
#define NTOK 4096
#define DMODEL 512
#define HH   8
#define DH   64
#define WW   128
#define PP   32
#define DISP 64

// ---------------------------------------------------------------------------
// Scratch (__device__ globals; allocation-free rule) — all fp16
// ---------------------------------------------------------------------------
__device__ __half g_q[BB*HH*PP*WW*DH];
__device__ __half g_k[BB*HH*PP*WW*DH];
__device__ __half g_v[BB*HH*PP*WW*DH];
__device__ __half g_xa[BB*NTOK*DMODEL];
__device__ __half g_wq[3*HH*DH*DMODEL];
__device__ __half g_wo[DMODEL*DMODEL];
__device__ __half g_ao[BB*NTOK*DMODEL];

__device__ __forceinline__ uint32_t smem_u32(const void* p) {
    uint32_t a;
    asm("{ .reg .u64 t; cvta.to.shared.u64 t, %1; cvt.u32.u64 %0, t; }"
        : "=r"(a) : "l"(p));
    return a;
}
__device__ __forceinline__ void mma16816h(float* d, const uint32_t* a,
                                          uint32_t b0, uint32_t b1) {
    asm volatile(
        "mma.sync.aligned.m16n8k16.row.col.f32.f16.f16.f32 "
        "{%0,%1,%2,%3}, {%4,%5,%6,%7}, {%8,%9}, {%0,%1,%2,%3};"
        : "+f"(d[0]), "+f"(d[1]), "+f"(d[2]), "+f"(d[3])
        : "r"(a[0]), "r"(a[1]), "r"(a[2]), "r"(a[3]), "r"(b0), "r"(b1));
}
__device__ __forceinline__ void ldsm_x4(uint32_t* r, uint32_t addr) {
    asm volatile("ldmatrix.sync.aligned.m8n8.x4.shared.b16 {%0,%1,%2,%3}, [%4];"
                 : "=r"(r[0]), "=r"(r[1]), "=r"(r[2]), "=r"(r[3]) : "r"(addr));
}
__device__ __forceinline__ void ldsm_x4t(uint32_t* r, uint32_t addr) {
    asm volatile("ldmatrix.sync.aligned.m8n8.x4.trans.shared.b16 {%0,%1,%2,%3}, [%4];"
                 : "=r"(r[0]), "=r"(r[1]), "=r"(r[2]), "=r"(r[3]) : "r"(addr));
}
__device__ __forceinline__ uint32_t pack_h2(float x, float y) {
    __half2 h; h.x = __float2half_rn(x); h.y = __float2half_rn(y);
    return *(uint32_t*)&h;
}

// ---------------------------------------------------------------------------
// Fused prepass (x4 vectorized)
// ---------------------------------------------------------------------------
#define NX (BB*NTOK*DMODEL)
#define NWQ (1536*512)
#define NWO (512*512)
#define NCONV4 ((NX + NWQ + NWO) / 4)

__global__ __launch_bounds__(256) void conv_all(const float* __restrict__ X,
                                                const float* __restrict__ Wqkv,
                                                const float* __restrict__ Wout) {
    int q = blockIdx.x * 256 + threadIdx.x;
    if (q >= NCONV4) return;
    int idx = q * 4;
    float4 v;
    __half* dst;
    if (idx < NX) {
        int r = idx >> 9, k = idx & 511;
        int b = r >> 12, n = r & 4095;
        v = *(const float4*)(X + (size_t)(b * NTOK + ((n + DISP) & 4095)) * DMODEL + k);
        dst = g_xa + idx;
    } else if (idx < NX + NWQ) {
        int i = idx - NX;
        int n = i >> 9, k = i & 511;
        const float* s = Wqkv + (size_t)k * 1536 + n;
        v.x = s[0]; v.y = s[1536]; v.z = s[2 * 1536]; v.w = s[3 * 1536];
        dst = g_wq + i;
    } else {
        int i = idx - NX - NWQ;
        int n = i >> 9, k = i & 511;
        const float* s = Wout + (size_t)k * 512 + n;
        v.x = s[0]; v.y = s[512]; v.z = s[2 * 512]; v.w = s[3 * 512];
        dst = g_wo + i;
    }
    uint2 o;
    o.x = pack_h2(v.x, v.y);
    o.y = pack_h2(v.z, v.w);
    *(uint2*)dst = o;
}

// ---------------------------------------------------------------------------
// single-pass fp16 mma.sync GEMM. Block tile 128x128, 4 warps (2x2) of 64x64.
// 3 CTAs/SM (12 warps = 3/SMSP) for LDS->HMMA latency hiding.
// K=512 in 8 chunks of 64, 2-stage cp.async.
// mode 0: Xr @ Wqkv -> q/k/v fp16 window layout
// mode 1: AO @ Wout (+bias) -> d_out with roll(+DISP)
// ---------------------------------------------------------------------------
#define KCH   64
#define TSTR  72
#define TILE_A_E (128*TSTR)
#define TILE_B_E (128*TSTR)
#define STAGE_E  (TILE_A_E + TILE_B_E)      // 18432 elems
#define GEMM_SMEM (2*STAGE_E*2)             // 73728 B

__global__ __launch_bounds__(128, 3) void gemm128(const float* __restrict__ bias,
                                                  float* __restrict__ Out, int mode) {
    extern __shared__ char smem_raw[];
    __half* smem = (__half*)smem_raw;
    const int tid = threadIdx.x;
    const int wid = tid >> 5;
    const int lid = tid & 31;
    const int row0 = blockIdx.y * 128;
    const int col0 = blockIdx.x * 128;
    const int wm = wid & 1, wn = wid >> 1;      // 2x2 warp grid
    const int g = lid >> 2, cq = lid & 3;

    const __half* A  = mode ? g_ao : g_xa;
    const __half* Bw = mode ? g_wo : g_wq;

    // one 64-wide k-chunk: A 128x64 + B 128x64 = 2048 16B-chunks / 128 thr = 16
    auto issue = [&](int ko, int buf) {
        const int kbase = ko * KCH;
        __half* st = smem + buf * STAGE_E;
#pragma unroll
        for (int i = 0; i < 16; i++) {
            const int cidx = tid + i * 128;          // 0..2047
            const __half* src;
            uint32_t dst;
            if (cidx < 1024) {
                const int r = cidx >> 3;
                const int c8 = cidx & 7;
                src = A + (size_t)(row0 + r) * 512 + kbase + c8 * 8;
                dst = smem_u32(st + r * TSTR + c8 * 8);
            } else {
                const int rem = cidx - 1024;
                const int r = rem >> 3;
                const int c8 = rem & 7;
                src = Bw + (size_t)(col0 + r) * 512 + kbase + c8 * 8;
                dst = smem_u32(st + TILE_A_E + r * TSTR + c8 * 8);
            }
            asm volatile("cp.async.cg.shared.global [%0], [%1], 16;"
                         :: "r"(dst), "l"(src));
        }
        asm volatile("cp.async.commit_group;");
    };

    float acc[4][8][4];
#pragma unroll
    for (int im = 0; im < 4; im++)
#pragma unroll
        for (int in_ = 0; in_ < 8; in_++)
#pragma unroll
            for (int e = 0; e < 4; e++) acc[im][in_][e] = 0.f;

    issue(0, 0);
    for (int ko = 0; ko < 8; ko++) {
        const int buf = ko & 1;
        if (ko + 1 < 8) {
            issue(ko + 1, buf ^ 1);
            asm volatile("cp.async.wait_group 1;");
        } else {
            asm volatile("cp.async.wait_group 0;");
        }
        __syncthreads();

        const __half* Ap = smem + buf * STAGE_E;
        const __half* Bp = Ap + TILE_A_E;

#pragma unroll
        for (int ks = 0; ks < 4; ks++) {
            const int kofs = ks * 16;
            uint32_t af[4][4];
#pragma unroll
            for (int im = 0; im < 4; im++) {
                const int rb = wm * 64 + im * 16 + g;
                af[im][0] = *(const uint32_t*)(Ap + rb * TSTR + kofs + cq * 2);
                af[im][1] = *(const uint32_t*)(Ap + (rb + 8) * TSTR + kofs + cq * 2);
                af[im][2] = *(const uint32_t*)(Ap + rb * TSTR + kofs + 8 + cq * 2);
                af[im][3] = *(const uint32_t*)(Ap + (rb + 8) * TSTR + kofs + 8 + cq * 2);
            }
#pragma unroll
            for (int in_ = 0; in_ < 8; in_++) {
                const int nr = wn * 64 + in_ * 8 + g;
                const uint32_t b0 = *(const uint32_t*)(Bp + nr * TSTR + kofs + cq * 2);
                const uint32_t b1 = *(const uint32_t*)(Bp + nr * TSTR + kofs + 8 + cq * 2);
#pragma unroll
                for (int im = 0; im < 4; im++)
                    mma16816h(acc[im][in_], af[im], b0, b1);
            }
        }
        __syncthreads();
    }

    // Epilogue
#pragma unroll
    for (int im = 0; im < 4; im++) {
#pragma unroll
        for (int in_ = 0; in_ < 8; in_++) {
            const int C0 = col0 + wn * 64 + in_ * 8 + cq * 2;
#pragma unroll
            for (int half = 0; half < 2; half++) {
                const int R = row0 + wm * 64 + im * 16 + g + half * 8;
                float vx = acc[im][in_][half * 2];
                float vy = acc[im][in_][half * 2 + 1];
                if (mode == 0) {
                    const int b2 = R >> 12, n2 = R & 4095;
                    const int w = n2 >> 5, jw = n2 & 31;
                    const int part = C0 >> 9;
                    const int h = (C0 & 511) >> 6;
                    const int dh = C0 & 63;
                    const size_t idx = (((size_t)((b2 * HH + h) * PP + jw)) * WW + w) * DH + dh;
                    __half* dst = (part == 0 ? g_q : part == 1 ? g_k : g_v);
                    *(uint32_t*)(dst + idx) = pack_h2(vx, vy);
                } else {
                    const int b2 = R >> 12, n2 = R & 4095;
                    const int dstn = (n2 + DISP) & 4095;
                    float2 v2;
                    v2.x = vx + __ldg(&bias[C0]);
                    v2.y = vy + __ldg(&bias[C0 + 1]);
                    *(float2*)(Out + (size_t)(b2 * NTOK + dstn) * DMODEL + C0) = v2;
                }
            }
        }
    }
}

// ---------------------------------------------------------------------------
// K2: tensor-core window attention (mask-split halves), all fp16 single-pass.
// ---------------------------------------------------------------------------
#define ATSTR 72
#define ATILE_E (WW*ATSTR)
#define ATILE_B (ATILE_E*2)
#define ATT_SMEM (1024 + 3*ATILE_B)          // 56320 B

__global__ __launch_bounds__(256) void attn_kernel(const float* __restrict__ pos_emb) {
    extern __shared__ char smem_raw[];
    float* slut = (float*)smem_raw;
    char* tiles = smem_raw + 1024;

    const int bid = blockIdx.x;
    const int tid = threadIdx.x;
    const int wid = tid >> 5;
    const int lid = tid & 31;
    const int g = lid >> 2, cq = lid & 3;

    if (tid < 2 * WW - 1) slut[tid] = pos_emb[tid];

    const size_t woff = (size_t)bid * (WW * DH);
    const char* srcs[3] = { (const char*)(g_q + woff), (const char*)(g_k + woff),
                            (const char*)(g_v + woff) };
#pragma unroll
    for (int arr = 0; arr < 3; arr++) {
        const char* src = srcs[arr];
        char* tb = tiles + arr * ATILE_B;
#pragma unroll
        for (int ii = 0; ii < 4; ii++) {
            const int idx = ii * 256 + tid;
            const int r = idx >> 3, c8 = idx & 7;
            const uint32_t dst = smem_u32(tb + (r * ATSTR + c8 * 8) * 2);
            asm volatile("cp.async.cg.shared.global [%0], [%1], 16;"
                         :: "r"(dst), "l"(src + (r * 64 + c8 * 8) * 2));
        }
    }
    asm volatile("cp.async.commit_group;");
    asm volatile("cp.async.wait_group 0;");
    __syncthreads();

    const uint32_t tiles0 = smem_u32(tiles);
    const uint32_t sqB = tiles0;
    const uint32_t skB = tiles0 + ATILE_B;
    const uint32_t svB = tiles0 + 2 * ATILE_B;

    const int half = wid >> 2;
    const int mrow = (wid & 3) * 16;
    const int qrow0 = half * 64 + mrow;
    const int kbase = half * 64;

    const int lrow = (lid & 7) + ((lid >> 3) & 1) * 8;
    const int lkad = (lid >> 4) * 8;
    const uint32_t qadd = (uint32_t)(((qrow0 + lrow) * ATSTR + lkad) * 2);
    const uint32_t kadd = (uint32_t)(((kbase + lrow) * ATSTR + lkad) * 2);
    const int vlrow = lid & 15;
    const int vcol = (lid >> 4) * 8;

    float S[8][4];
#pragma unroll
    for (int nt = 0; nt < 8; nt++)
#pragma unroll
        for (int e = 0; e < 4; e++) S[nt][e] = 0.f;

#pragma unroll
    for (int ks = 0; ks < 4; ks++) {
        const uint32_t kofsB = ks * 32;
        uint32_t aq[4], kb[4][4];
        ldsm_x4(aq, sqB + qadd + kofsB);
#pragma unroll
        for (int j = 0; j < 4; j++)
            ldsm_x4(kb[j], skB + kadd + j * (16 * ATSTR * 2) + kofsB);
#pragma unroll
        for (int nt = 0; nt < 8; nt++) {
            const uint32_t b0 = kb[nt >> 1][nt & 1];
            const uint32_t b1 = kb[nt >> 1][2 + (nt & 1)];
            mma16816h(S[nt], aq, b0, b1);
        }
    }

    const float scale = 0.125f;
    const int il0 = mrow + g;
    const int il1 = il0 + 8;
    float rs0 = 0.f, rs1 = 0.f;
#pragma unroll
    for (int nt = 0; nt < 8; nt++) {
        const int jl = nt * 8 + cq * 2;
        float p0 = __expf(S[nt][0] * scale + slut[jl - il0 + (WW - 1)]);
        float p1 = __expf(S[nt][1] * scale + slut[jl + 1 - il0 + (WW - 1)]);
        float p2 = __expf(S[nt][2] * scale + slut[jl - il1 + (WW - 1)]);
        float p3 = __expf(S[nt][3] * scale + slut[jl + 1 - il1 + (WW - 1)]);
        S[nt][0] = p0; S[nt][1] = p1; S[nt][2] = p2; S[nt][3] = p3;
        rs0 += p0 + p1;
        rs1 += p2 + p3;
    }
    rs0 += __shfl_xor_sync(0xFFFFFFFF, rs0, 1);
    rs0 += __shfl_xor_sync(0xFFFFFFFF, rs0, 2);
    rs1 += __shfl_xor_sync(0xFFFFFFFF, rs1, 1);
    rs1 += __shfl_xor_sync(0xFFFFFFFF, rs1, 2);
    const float inv0 = 1.0f / rs0;
    const float inv1 = 1.0f / rs1;

    uint32_t pf[4][4];
#pragma unroll
    for (int ks = 0; ks < 4; ks++) {
        pf[ks][0] = pack_h2(S[2 * ks][0],     S[2 * ks][1]);
        pf[ks][1] = pack_h2(S[2 * ks][2],     S[2 * ks][3]);
        pf[ks][2] = pack_h2(S[2 * ks + 1][0], S[2 * ks + 1][1]);
        pf[ks][3] = pack_h2(S[2 * ks + 1][2], S[2 * ks + 1][3]);
    }

    float O[8][4];
#pragma unroll
    for (int nt = 0; nt < 8; nt++)
#pragma unroll
        for (int e = 0; e < 4; e++) O[nt][e] = 0.f;

#pragma unroll
    for (int ks = 0; ks < 4; ks++) {
        const int vrow16 = kbase + ks * 16 + vlrow;
#pragma unroll
        for (int j = 0; j < 4; j++) {
            uint32_t v0[4];
            const uint32_t vaddr = (uint32_t)((vrow16 * ATSTR + j * 16 + vcol) * 2);
            ldsm_x4t(v0, svB + vaddr);
            mma16816h(O[2 * j],     pf[ks], v0[0], v0[1]);
            mma16816h(O[2 * j + 1], pf[ks], v0[2], v0[3]);
        }
    }

    const int b  = bid >> 8;
    const int h  = (bid >> 5) & 7;
    const int jw = bid & 31;
    const int iw0 = half * 64 + il0;
    const int iw1 = half * 64 + il1;
    const size_t row0off = ((size_t)(b * NTOK + jw * WW + iw0)) * DMODEL + h * DH;
    const size_t row1off = ((size_t)(b * NTOK + jw * WW + iw1)) * DMODEL + h * DH;
#pragma unroll
    for (int nt = 0; nt < 8; nt++) {
        const int c = nt * 8 + cq * 2;
        *(uint32_t*)(g_ao + row0off + c) = pack_h2(O[nt][0] * inv0, O[nt][1] * inv0);
        *(uint32_t*)(g_ao + row1off + c) = pack_h2(O[nt][2] * inv1, O[nt][3] * inv1);
    }
}

// ---------------------------------------------------------------------------
extern "C" void kernel_launch(void* const* d_in, const int* in_sizes, int n_in,
                              void* d_out, int out_size) {
    const float* x       = (const float*)d_in[0];
    const float* Wqkv    = (const float*)d_in[1];
    const float* pos_emb = (const float*)d_in[2];
    const float* Wout    = (const float*)d_in[3];
    const float* bout    = (const float*)d_in[4];
    float* out = (float*)d_out;

    cudaFuncSetAttribute(gemm128, cudaFuncAttributeMaxDynamicSharedMemorySize, GEMM_SMEM);
    cudaFuncSetAttribute(attn_kernel, cudaFuncAttributeMaxDynamicSharedMemorySize, ATT_SMEM);

    conv_all<<<(NCONV4 + 255) / 256, 256>>>(x, Wqkv, Wout);

    // K1: QKV (M=32768 -> 256 row blocks, N=1536 -> 12 col blocks)
    gemm128<<<dim3(12, 256), 128, GEMM_SMEM>>>(nullptr, nullptr, 0);
    // K2: attention, one window per block
    attn_kernel<<<2048, 256, ATT_SMEM>>>(pos_emb);
    // K3: output projection (N=512 -> 4 col blocks) + bias + roll
    gemm128<<<dim3(4, 256), 128, GEMM_SMEM>>>(bout, out, 1);
}